// round 9
// baseline (speedup 1.0000x reference)
#include <cuda_runtime.h>
#include <cuda_bf16.h>
#include <cstdint>

// ---------------------------------------------------------------------------
// S4D model forward:  encoder GEMM -> 4x( S4 scan+gelu -> GEMM -> GLU+res+LN )
//                     -> decoder
// GEMMs: mma.sync m16n8k16 bf16, 3-pass hi/lo split, operands PRE-SPLIT to
//        bf16 planes by producers; cp.async 3-stage pipeline; 2 CTAs/SM.
// Scan:  time-chunked (8 chunks) 3-phase linear-recurrence decomposition,
//        packed fp32x2 FMA; epilogue emits bf16 hi/lo planes for the GEMM.
// ---------------------------------------------------------------------------

#define BSZ    32
#define LSEQ   1024
#define DIN    128
#define HDIM   256
#define NL     4
#define NMODE  32
#define DOUT   10
#define MROWS  (BSZ * LSEQ)          // 32768
#define HN     (HDIM * NMODE)        // 8192
#define NCH    8                     // time chunks
#define CHL    (LSEQ / NCH)          // 128 steps per chunk

// Scratch (device globals; no allocation allowed)
__device__ __align__(128) float g_h[MROWS * HDIM];
__device__ __align__(128) float g_z[MROWS * 2 * HDIM];
__device__ __align__(128) float g_coef[NL * 8 * HN];
__device__ __align__(128) float g_sre[BSZ * NCH * HN];
__device__ __align__(128) float g_sim[BSZ * NCH * HN];
__device__ __align__(16) __nv_bfloat16 g_yhi[MROWS * HDIM];
__device__ __align__(16) __nv_bfloat16 g_ylo[MROWS * HDIM];
__device__ __align__(16) __nv_bfloat16 g_xhi[MROWS * DIN];
__device__ __align__(16) __nv_bfloat16 g_xlo[MROWS * DIN];
__device__ __align__(16) __nv_bfloat16 g_wthi_enc[HDIM * DIN];
__device__ __align__(16) __nv_bfloat16 g_wtlo_enc[HDIM * DIN];
__device__ __align__(16) __nv_bfloat16 g_wthi[NL * 2 * HDIM * HDIM];
__device__ __align__(16) __nv_bfloat16 g_wtlo[NL * 2 * HDIM * HDIM];

typedef unsigned long long ull;

__device__ __forceinline__ ull pack2(float x) {
    ull r; asm("mov.b64 %0, {%1, %1};" : "=l"(r) : "f"(x)); return r;
}
__device__ __forceinline__ ull packf(float a, float b) {
    ull r; asm("mov.b64 %0, {%1, %2};" : "=l"(r) : "f"(a), "f"(b)); return r;
}
__device__ __forceinline__ ull fma2(ull a, ull b, ull c) {
    ull d; asm("fma.rn.f32x2 %0, %1, %2, %3;" : "=l"(d) : "l"(a), "l"(b), "l"(c)); return d;
}
union U2 { ull u; float2 f; };

__device__ __forceinline__ uint32_t smem_u32(const void* p) {
    uint32_t a;
    asm("{ .reg .u64 t; cvta.to.shared.u64 t, %1; cvt.u32.u64 %0, t; }"
        : "=r"(a) : "l"(p));
    return a;
}
__device__ __forceinline__ void ldsm4(uint32_t* r, uint32_t addr) {
    asm volatile("ldmatrix.sync.aligned.m8n8.x4.shared.b16 {%0,%1,%2,%3}, [%4];"
                 : "=r"(r[0]), "=r"(r[1]), "=r"(r[2]), "=r"(r[3]) : "r"(addr));
}
__device__ __forceinline__ void mma16816(float* c, const uint32_t* a, const uint32_t* b) {
    asm volatile("mma.sync.aligned.m16n8k16.row.col.f32.bf16.bf16.f32 "
                 "{%0,%1,%2,%3}, {%4,%5,%6,%7}, {%8,%9}, {%0,%1,%2,%3};"
                 : "+f"(c[0]), "+f"(c[1]), "+f"(c[2]), "+f"(c[3])
                 : "r"(a[0]), "r"(a[1]), "r"(a[2]), "r"(a[3]), "r"(b[0]), "r"(b[1]));
}
__device__ __forceinline__ void cpasync16(uint32_t d, const void* s) {
    asm volatile("cp.async.cg.shared.global [%0], [%1], 16;" :: "r"(d), "l"(s));
}

__device__ __forceinline__ float gelu_f(float x) {
    float x3 = x * x * x;
    float t  = tanhf(0.7978845608028654f * fmaf(0.044715f, x3, x));
    return 0.5f * x * (1.0f + t);
}

// ---------------------------------------------------------------------------
// Discretization prep.  Planes: 0 dAre, 1 dAim, 2 dBre, 3 dBim, 4 2Cre,
// 5 -2Cim, 6/7 = (dA^CHL) re/im.
// ---------------------------------------------------------------------------
__global__ void prep_coef(const float* __restrict__ log_dt,
                          const float* __restrict__ A_re_log,
                          const float* __restrict__ A_im,
                          const float* __restrict__ B_re,
                          const float* __restrict__ B_im,
                          const float* __restrict__ C_re,
                          const float* __restrict__ C_im)
{
    int t = blockIdx.x * 256 + threadIdx.x;
    if (t >= NL * HN) return;
    int l  = t / HN;
    int hn = t - l * HN;
    int hh = hn / NMODE;

    float Are = -expf(A_re_log[t]);
    float Aim = A_im[t];
    float dt  = expf(log_dt[l * HDIM + hh]);
    float dre = dt * Are, dim = dt * Aim;
    float e   = expf(dre);
    float dAre = e * cosf(dim);
    float dAim = e * sinf(dim);
    float nre = dAre - 1.0f, nim = dAim;
    float inv = 1.0f / (Are * Are + Aim * Aim);
    float qre = (nre * Are + nim * Aim) * inv;
    float qim = (nim * Are - nre * Aim) * inv;
    float bre = B_re[t], bim = B_im[t];
    float dBre = bre * qre - bim * qim;
    float dBim = bre * qim + bim * qre;

    float eL = expf((float)CHL * dre);
    float cL = cosf((float)CHL * dim);
    float sL = sinf((float)CHL * dim);

    float* cf = g_coef + (size_t)l * 8 * HN;
    cf[0 * HN + hn] = dAre;
    cf[1 * HN + hn] = dAim;
    cf[2 * HN + hn] = dBre;
    cf[3 * HN + hn] = dBim;
    cf[4 * HN + hn] =  2.0f * C_re[t];
    cf[5 * HN + hn] = -2.0f * C_im[t];
    cf[6 * HN + hn] = eL * cL;
    cf[7 * HN + hn] = eL * sL;
}

// ---------------------------------------------------------------------------
// Weight transpose + bf16 hi/lo split:  W [K][N] fp32 -> Whi/Wlo [N][K] bf16
// ---------------------------------------------------------------------------
__global__ void split_w(const float* __restrict__ W,
                        __nv_bfloat16* __restrict__ Whi,
                        __nv_bfloat16* __restrict__ Wlo, int K, int N)
{
    __shared__ float t[32][33];
    int n0 = blockIdx.x * 32, k0 = blockIdx.y * 32;
    const float* Wp = W + (size_t)blockIdx.z * K * N;
    __nv_bfloat16* Hp = Whi + (size_t)blockIdx.z * K * N;
    __nv_bfloat16* Lp = Wlo + (size_t)blockIdx.z * K * N;
#pragma unroll
    for (int yy = 0; yy < 32; yy += 8)
        t[threadIdx.y + yy][threadIdx.x] =
            Wp[(size_t)(k0 + threadIdx.y + yy) * N + n0 + threadIdx.x];
    __syncthreads();
#pragma unroll
    for (int yy = 0; yy < 32; yy += 8) {
        float v = t[threadIdx.x][threadIdx.y + yy];
        __nv_bfloat16 h = __float2bfloat16_rn(v);
        float r = v - __bfloat162float(h);
        size_t o = (size_t)(n0 + threadIdx.y + yy) * K + k0 + threadIdx.x;
        Hp[o] = h;
        Lp[o] = __float2bfloat16_rn(r);
    }
}

// Activation split (row-major, no transpose): A fp32 -> hi/lo bf16
__global__ void split_act(const float* __restrict__ A,
                          __nv_bfloat16* __restrict__ Hi,
                          __nv_bfloat16* __restrict__ Lo, int n4)
{
    int i = blockIdx.x * 256 + threadIdx.x;
    if (i >= n4) return;
    float4 v = ((const float4*)A)[i];
    __nv_bfloat16 h0 = __float2bfloat16_rn(v.x), h1 = __float2bfloat16_rn(v.y);
    __nv_bfloat16 h2 = __float2bfloat16_rn(v.z), h3 = __float2bfloat16_rn(v.w);
    ushort4 hv = make_ushort4(__bfloat16_as_ushort(h0), __bfloat16_as_ushort(h1),
                              __bfloat16_as_ushort(h2), __bfloat16_as_ushort(h3));
    ushort4 lv = make_ushort4(
        __bfloat16_as_ushort(__float2bfloat16_rn(v.x - __bfloat162float(h0))),
        __bfloat16_as_ushort(__float2bfloat16_rn(v.y - __bfloat162float(h1))),
        __bfloat16_as_ushort(__float2bfloat16_rn(v.z - __bfloat162float(h2))),
        __bfloat16_as_ushort(__float2bfloat16_rn(v.w - __bfloat162float(h3))));
    ((ushort4*)Hi)[i] = hv;
    ((ushort4*)Lo)[i] = lv;
}

// ---------------------------------------------------------------------------
// bf16 split-3 tensor-core GEMM, all operands pre-split bf16 planes.
//   C[M,N] = (Ahi+Alo)[M,K] @ (Whi+Wlo)^T + bias  (3 products, fp32 acc)
//   BM=BN=128, BK=32, 256 thr (8 warps = 4Mx2N), cp.async 3-stage pipeline.
//   Stage layout (32KB): [Ahi 8K][Alo 8K][Bhi 8K][Blo 8K], rows of 64B,
//   16B chunk c of row r stored at c ^ ((r>>1)&3).
// ---------------------------------------------------------------------------
#define NS 3
template <int K>
__global__ __launch_bounds__(256, 2) void mma_gemm(
    const __nv_bfloat16* __restrict__ Ahi, const __nv_bfloat16* __restrict__ Alo,
    const __nv_bfloat16* __restrict__ Bhi, const __nv_bfloat16* __restrict__ Blo,
    const float* __restrict__ bias, float* __restrict__ C, int N)
{
    constexpr int KCH = K / 32;
    extern __shared__ char sm[];
    const uint32_t sbase = smem_u32(sm);

    const int tid  = threadIdx.x;
    const int warp = tid >> 5, lane = tid & 31;
    const int wm = warp >> 1, wn = warp & 1;
    const size_t m0 = (size_t)blockIdx.y * 128;
    const int    n0 = blockIdx.x * 128;

    // copy role: plane = tid>>6 (0 Ahi,1 Alo,2 Bhi,3 Blo), rows trow, trow+1
    const int tp   = tid >> 6;
    const int trow = (tid & 63) * 2;
    const __nv_bfloat16* pl =
        (tp == 0) ? Ahi + (m0 + trow) * K :
        (tp == 1) ? Alo + (m0 + trow) * K :
        (tp == 2) ? Bhi + (size_t)(n0 + trow) * K :
                    Blo + (size_t)(n0 + trow) * K;
    const uint32_t xsw   = (uint32_t)(trow >> 1) & 3;
    const uint32_t dbase = tp * 8192 + trow * 64;

    auto issue = [&](int cs) {
        uint32_t st = sbase + (cs % NS) * 32768 + dbase;
        const __nv_bfloat16* s0 = pl + cs * 32;
#pragma unroll
        for (int r = 0; r < 2; r++)
#pragma unroll
            for (int c = 0; c < 4; c++)
                cpasync16(st + r * 64 + (((uint32_t)c ^ xsw) << 4),
                          s0 + r * K + c * 8);
        asm volatile("cp.async.commit_group;");
    };

    float acc[2][8][4];
#pragma unroll
    for (int a = 0; a < 2; a++)
#pragma unroll
        for (int b = 0; b < 8; b++)
#pragma unroll
            for (int c = 0; c < 4; c++) acc[a][b][c] = 0.f;

    auto compute = [&](int buf) {
        uint32_t ab = sbase + buf * 32768;
#pragma unroll
        for (int ks = 0; ks < 2; ks++) {
            uint32_t ah[2][4], al[2][4], bh[8][2], bl[8][2];
#pragma unroll
            for (int mt = 0; mt < 2; mt++) {
                int r  = wm * 32 + mt * 16 + (lane & 15);
                int ch = ks * 2 + (lane >> 4);
                uint32_t addr = ab + r * 64 + ((ch ^ ((r >> 1) & 3)) << 4);
                ldsm4(ah[mt], addr);
                ldsm4(al[mt], addr + 8192);
            }
#pragma unroll
            for (int j = 0; j < 4; j++) {
                int r  = wn * 64 + j * 16 + (lane & 15);
                int ch = ks * 2 + (lane >> 4);
                uint32_t addr = ab + 16384 + r * 64 + ((ch ^ ((r >> 1) & 3)) << 4);
                uint32_t q[4];
                ldsm4(q, addr);
                bh[2 * j][0] = q[0]; bh[2 * j + 1][0] = q[1];
                bh[2 * j][1] = q[2]; bh[2 * j + 1][1] = q[3];
                ldsm4(q, addr + 8192);
                bl[2 * j][0] = q[0]; bl[2 * j + 1][0] = q[1];
                bl[2 * j][1] = q[2]; bl[2 * j + 1][1] = q[3];
            }
#pragma unroll
            for (int mt = 0; mt < 2; mt++)
#pragma unroll
                for (int nt = 0; nt < 8; nt++) {
                    mma16816(acc[mt][nt], ah[mt], bh[nt]);
                    mma16816(acc[mt][nt], al[mt], bh[nt]);
                    mma16816(acc[mt][nt], ah[mt], bl[nt]);
                }
        }
    };

    issue(0);
    issue(1);
    for (int c = 0; c < KCH; c++) {
        asm volatile("cp.async.wait_group 1;" ::: "memory");
        __syncthreads();
        compute(c % NS);
        if (c + 2 < KCH) issue(c + 2);
        else             asm volatile("cp.async.commit_group;");
    }

#pragma unroll
    for (int mt = 0; mt < 2; mt++) {
#pragma unroll
        for (int nt = 0; nt < 8; nt++) {
            int r = (int)m0 + wm * 32 + mt * 16 + (lane >> 2);
            int n = n0 + wn * 64 + nt * 8 + (lane & 3) * 2;
            float b0 = bias[n], b1 = bias[n + 1];
            *(float2*)(C + (size_t)r * N + n) =
                make_float2(acc[mt][nt][0] + b0, acc[mt][nt][1] + b1);
            *(float2*)(C + (size_t)(r + 8) * N + n) =
                make_float2(acc[mt][nt][2] + b0, acc[mt][nt][3] + b1);
        }
    }
}

// ---------------------------------------------------------------------------
// Scan lane mapping (phases A and C): block = 128 thr owns (batch, 32 chans,
// one time chunk).  4 lanes per channel, 8 modes per lane (4 packed pairs).
// ---------------------------------------------------------------------------
#define SCAN_COEF_LOAD(NP)                                                    \
    ull dAre2[NP], dAim2[NP], ndAim2[NP], dBre2[NP], dBim2[NP];               \
    _Pragma("unroll")                                                         \
    for (int p = 0; p < NP; p++) {                                            \
        int c0 = hh * NMODE + mg + 2 * p;                                     \
        dAre2[p]  = packf(cf[0 * HN + c0], cf[0 * HN + c0 + 1]);              \
        dAim2[p]  = packf(cf[1 * HN + c0], cf[1 * HN + c0 + 1]);              \
        ndAim2[p] = packf(-cf[1 * HN + c0], -cf[1 * HN + c0 + 1]);            \
        dBre2[p]  = packf(cf[2 * HN + c0], cf[2 * HN + c0 + 1]);              \
        dBim2[p]  = packf(cf[3 * HN + c0], cf[3 * HN + c0 + 1]);              \
    }

// Phase A: local end-state per chunk (zero init), chunks 0..NCH-2
__global__ __launch_bounds__(128) void s4_state(
    const float* __restrict__ u, const float* __restrict__ cf)
{
    const int b     = blockIdx.y;
    const int chunk = blockIdx.z;
    const int h0    = blockIdx.x * 32;
    const int tid   = threadIdx.x;
    const int w     = tid >> 5;
    const int lane  = tid & 31;
    const int hcol  = (w << 3) + (lane >> 2);
    const int mg    = (lane & 3) * 8;
    const int hh    = h0 + hcol;

    SCAN_COEF_LOAD(4)

    __shared__ float su[64 * 32];
    ull sre2[4] = {0ull, 0ull, 0ull, 0ull};
    ull sim2[4] = {0ull, 0ull, 0ull, 0ull};

    const float* ub = u + ((size_t)b * LSEQ + (size_t)chunk * CHL) * HDIM + h0;

    for (int l0 = 0; l0 < CHL; l0 += 64) {
        __syncthreads();
#pragma unroll
        for (int k = 0; k < 16; k++) {
            int e = tid + k * 128;
            su[e] = ub[(size_t)(l0 + (e >> 5)) * HDIM + (e & 31)];
        }
        __syncthreads();
#pragma unroll 4
        for (int i = 0; i < 64; i++) {
            ull uu2 = pack2(su[i * 32 + hcol]);
#pragma unroll
            for (int p = 0; p < 4; p++) {
                ull mre = fma2(dBre2[p], uu2, 0ull);
                ull mim = fma2(dBim2[p], uu2, 0ull);
                ull nre = fma2(ndAim2[p], sim2[p], mre);
                nre     = fma2(dAre2[p],  sre2[p], nre);
                ull nim = fma2(dAim2[p],  sre2[p], mim);
                nim     = fma2(dAre2[p],  sim2[p], nim);
                sre2[p] = nre; sim2[p] = nim;
            }
        }
    }
    size_t sidx = ((size_t)b * NCH + chunk) * HN + hh * NMODE + mg;
#pragma unroll
    for (int p = 0; p < 4; p++) {
        U2 r, q; r.u = sre2[p]; q.u = sim2[p];
        g_sre[sidx + 2 * p]     = r.f.x;
        g_sre[sidx + 2 * p + 1] = r.f.y;
        g_sim[sidx + 2 * p]     = q.f.x;
        g_sim[sidx + 2 * p + 1] = q.f.y;
    }
}

// Phase B: cross-chunk scan (in place): end-states -> init states
__global__ __launch_bounds__(256) void s4_fix(const float* __restrict__ cf)
{
    int t = blockIdx.x * 256 + threadIdx.x;
    if (t >= BSZ * HN) return;
    int b  = t / HN;
    int hn = t - b * HN;
    float pre = cf[6 * HN + hn], pim = cf[7 * HN + hn];
    float Sre = 0.f, Sim = 0.f;
#pragma unroll
    for (int c = 0; c < NCH; c++) {
        size_t idx = ((size_t)b * NCH + c) * HN + hn;
        float ere = 0.f, eim = 0.f;
        if (c < NCH - 1) { ere = g_sre[idx]; eim = g_sim[idx]; }
        g_sre[idx] = Sre;
        g_sim[idx] = Sim;
        float nr = fmaf(pre, Sre, fmaf(-pim, Sim, ere));
        float ni = fmaf(pre, Sim, fmaf(pim, Sre, eim));
        Sre = nr; Sim = ni;
    }
}

// Phase C: full per-chunk scan with init state -> gelu(y + D*u), emitted as
// bf16 hi/lo planes for the downstream GEMM.
__global__ __launch_bounds__(128) void s4_scan_out(
    const float* __restrict__ u,
    __nv_bfloat16* __restrict__ yhi, __nv_bfloat16* __restrict__ ylo,
    const float* __restrict__ cf, const float* __restrict__ Dv)
{
    const int b     = blockIdx.y;
    const int chunk = blockIdx.z;
    const int h0    = blockIdx.x * 32;
    const int tid   = threadIdx.x;
    const int w     = tid >> 5;
    const int lane  = tid & 31;
    const int hcol  = (w << 3) + (lane >> 2);
    const int mg    = (lane & 3) * 8;
    const int hh    = h0 + hcol;

    SCAN_COEF_LOAD(4)
    ull c2re2[4], c2in2[4];
#pragma unroll
    for (int p = 0; p < 4; p++) {
        int c0 = hh * NMODE + mg + 2 * p;
        c2re2[p] = packf(cf[4 * HN + c0], cf[4 * HN + c0 + 1]);
        c2in2[p] = packf(cf[5 * HN + c0], cf[5 * HN + c0 + 1]);
    }

    __shared__ float su[64 * 32];
    __shared__ float sy[64 * 32];
    __shared__ float sD[32];
    if (tid < 32) sD[tid] = Dv[h0 + tid];

    ull sre2[4], sim2[4];
    {
        size_t sidx = ((size_t)b * NCH + chunk) * HN + hh * NMODE + mg;
#pragma unroll
        for (int p = 0; p < 4; p++) {
            sre2[p] = packf(g_sre[sidx + 2 * p], g_sre[sidx + 2 * p + 1]);
            sim2[p] = packf(g_sim[sidx + 2 * p], g_sim[sidx + 2 * p + 1]);
        }
    }

    const size_t rbase = ((size_t)b * LSEQ + (size_t)chunk * CHL) * HDIM + h0;
    const float* ub = u + rbase;
    __nv_bfloat16* yh = yhi + rbase;
    __nv_bfloat16* yl = ylo + rbase;

    for (int l0 = 0; l0 < CHL; l0 += 64) {
        __syncthreads();
#pragma unroll
        for (int k = 0; k < 16; k++) {
            int e = tid + k * 128;
            su[e] = ub[(size_t)(l0 + (e >> 5)) * HDIM + (e & 31)];
        }
        __syncthreads();
#pragma unroll 2
        for (int i = 0; i < 64; i++) {
            ull uu2  = pack2(su[i * 32 + hcol]);
            ull cacc = 0ull;
#pragma unroll
            for (int p = 0; p < 4; p++) {
                ull mre = fma2(dBre2[p], uu2, 0ull);
                ull mim = fma2(dBim2[p], uu2, 0ull);
                ull nre = fma2(ndAim2[p], sim2[p], mre);
                nre     = fma2(dAre2[p],  sre2[p], nre);
                ull nim = fma2(dAim2[p],  sre2[p], mim);
                nim     = fma2(dAre2[p],  sim2[p], nim);
                sre2[p] = nre; sim2[p] = nim;
                cacc = fma2(c2re2[p], nre, cacc);
                cacc = fma2(c2in2[p], nim, cacc);
            }
            U2 cu; cu.u = cacc;
            float c = cu.f.x + cu.f.y;
            c += __shfl_xor_sync(0xffffffffu, c, 1);
            c += __shfl_xor_sync(0xffffffffu, c, 2);
            if ((lane & 3) == 0) sy[i * 32 + hcol] = c;
        }
        __syncthreads();
#pragma unroll
        for (int k = 0; k < 16; k++) {
            int e = tid + k * 128;
            float t = sy[e] + sD[e & 31] * su[e];
            float g = gelu_f(t);
            __nv_bfloat16 hi = __float2bfloat16_rn(g);
            size_t o = (size_t)(l0 + (e >> 5)) * HDIM + (e & 31);
            yh[o] = hi;
            yl[o] = __float2bfloat16_rn(g - __bfloat162float(hi));
        }
    }
}

// ---------------------------------------------------------------------------
// GLU + residual + LayerNorm (in-place on h).  Warp per row of 256.
// ---------------------------------------------------------------------------
__global__ __launch_bounds__(256) void glu_res_ln(
    const float* __restrict__ z, float* __restrict__ h,
    const float* __restrict__ lnw, const float* __restrict__ lnb)
{
    const int row  = blockIdx.x * 8 + (threadIdx.x >> 5);
    const int lane = threadIdx.x & 31;
    const float* zr = z + (size_t)row * (2 * HDIM);
    float*       hr = h + (size_t)row * HDIM;

    float tv[8];
    float s = 0.f, s2 = 0.f;
#pragma unroll
    for (int k = 0; k < 8; k++) {
        int c = lane + k * 32;
        float a  = zr[c];
        float gg = zr[HDIM + c];
        float t  = a / (1.0f + expf(-gg)) + hr[c];
        tv[k] = t;
        s  += t;
        s2  = fmaf(t, t, s2);
    }
#pragma unroll
    for (int o = 16; o; o >>= 1) {
        s  += __shfl_xor_sync(0xffffffffu, s,  o);
        s2 += __shfl_xor_sync(0xffffffffu, s2, o);
    }
    float mean = s * (1.0f / 256.0f);
    float var  = fmaf(-mean, mean, s2 * (1.0f / 256.0f));
    float rs   = rsqrtf(var + 1e-5f);
#pragma unroll
    for (int k = 0; k < 8; k++) {
        int c = lane + k * 32;
        hr[c] = fmaf((tv[k] - mean) * rs, lnw[c], lnb[c]);
    }
}

// ---------------------------------------------------------------------------
// Decoder: out[M,10] = h[M,256] @ dec_w[256,10] + dec_b
// ---------------------------------------------------------------------------
__global__ __launch_bounds__(256) void decoder(
    const float* __restrict__ h, const float* __restrict__ wv,
    const float* __restrict__ bvec, float* __restrict__ out)
{
    __shared__ float sw[HDIM * DOUT];
    for (int i = threadIdx.x; i < HDIM * DOUT; i += 256) sw[i] = wv[i];
    __syncthreads();
    int o = blockIdx.x * 256 + threadIdx.x;
    int r = o / DOUT, n = o - r * DOUT;
    const float* hr = h + (size_t)r * HDIM;
    float s = bvec[n];
#pragma unroll 8
    for (int k = 0; k < HDIM; k++) s = fmaf(hr[k], sw[k * DOUT + n], s);
    out[o] = s;
}

// ---------------------------------------------------------------------------
extern "C" void kernel_launch(void* const* d_in, const int* in_sizes, int n_in,
                              void* d_out, int out_size)
{
    const float* x        = (const float*)d_in[0];
    const float* enc_w    = (const float*)d_in[1];
    const float* enc_b    = (const float*)d_in[2];
    const float* log_dt   = (const float*)d_in[3];
    const float* A_re_log = (const float*)d_in[4];
    const float* A_im     = (const float*)d_in[5];
    const float* B_re     = (const float*)d_in[6];
    const float* B_im     = (const float*)d_in[7];
    const float* C_re     = (const float*)d_in[8];
    const float* C_im     = (const float*)d_in[9];
    const float* Dp       = (const float*)d_in[10];
    const float* ln_w     = (const float*)d_in[11];
    const float* ln_b     = (const float*)d_in[12];
    const float* out_w    = (const float*)d_in[13];
    const float* out_b    = (const float*)d_in[14];
    const float* dec_w    = (const float*)d_in[15];
    const float* dec_b    = (const float*)d_in[16];
    float* outp = (float*)d_out;

    float *ph, *pz, *pcf;
    __nv_bfloat16 *pyh, *pyl, *pxh, *pxl, *pwhE, *pwlE, *pwh, *pwl;
    cudaGetSymbolAddress((void**)&ph,  g_h);
    cudaGetSymbolAddress((void**)&pz,  g_z);
    cudaGetSymbolAddress((void**)&pcf, g_coef);
    cudaGetSymbolAddress((void**)&pyh, g_yhi);
    cudaGetSymbolAddress((void**)&pyl, g_ylo);
    cudaGetSymbolAddress((void**)&pxh, g_xhi);
    cudaGetSymbolAddress((void**)&pxl, g_xlo);
    cudaGetSymbolAddress((void**)&pwhE, g_wthi_enc);
    cudaGetSymbolAddress((void**)&pwlE, g_wtlo_enc);
    cudaGetSymbolAddress((void**)&pwh, g_wthi);
    cudaGetSymbolAddress((void**)&pwl, g_wtlo);

    cudaFuncSetAttribute(mma_gemm<128>,
                         cudaFuncAttributeMaxDynamicSharedMemorySize, NS * 32768);
    cudaFuncSetAttribute(mma_gemm<256>,
                         cudaFuncAttributeMaxDynamicSharedMemorySize, NS * 32768);

    prep_coef<<<(NL * HN + 255) / 256, 256>>>(log_dt, A_re_log, A_im,
                                              B_re, B_im, C_re, C_im);
    split_w<<<dim3(HDIM / 32, DIN / 32, 1), dim3(32, 8)>>>(enc_w, pwhE, pwlE,
                                                           DIN, HDIM);
    split_w<<<dim3(2 * HDIM / 32, HDIM / 32, NL), dim3(32, 8)>>>(out_w, pwh, pwl,
                                                                 HDIM, 2 * HDIM);
    split_act<<<(MROWS * DIN / 4 + 255) / 256, 256>>>(x, pxh, pxl, MROWS * DIN / 4);

    // encoder: h = x @ enc_w + enc_b   (M=32768, N=256, K=128)
    mma_gemm<128><<<dim3(2, MROWS / 128), 256, NS * 32768>>>(
        pxh, pxl, pwhE, pwlE, enc_b, ph, HDIM);

    for (int l = 0; l < NL; l++) {
        const float* cfl = pcf + (size_t)l * 8 * HN;
        s4_state<<<dim3(HDIM / 32, BSZ, NCH - 1), 128>>>(ph, cfl);
        s4_fix<<<(BSZ * HN + 255) / 256, 256>>>(cfl);
        s4_scan_out<<<dim3(HDIM / 32, BSZ, NCH), 128>>>(ph, pyh, pyl, cfl,
                                                        Dp + l * HDIM);
        mma_gemm<256><<<dim3(4, MROWS / 128), 256, NS * 32768>>>(
            pyh, pyl,
            pwh + (size_t)l * 2 * HDIM * HDIM,
            pwl + (size_t)l * 2 * HDIM * HDIM,
            out_b + l * 2 * HDIM, pz, 2 * HDIM);
        glu_res_ln<<<MROWS / 8, 256>>>(pz, ph, ln_w + l * HDIM, ln_b + l * HDIM);
    }

    decoder<<<(MROWS * DOUT) / 256, 256>>>(ph, dec_w, dec_b, outp);
}

// round 12
// speedup vs baseline: 1.0187x; 1.0187x over previous
#include <cuda_runtime.h>
#include <cuda_bf16.h>
#include <cstdint>

// ---------------------------------------------------------------------------
// S4D model forward:  encoder GEMM -> 4x( S4 scan+gelu -> GEMM -> GLU+res+LN )
//                     -> decoder
// GEMMs: mma.sync m16n8k16 bf16, 3-pass hi/lo split, 2 CTAs/SM (R6-proven).
// Scan:  time-chunked (16 chunks) 3-phase linear-recurrence decomposition,
//        packed fp32x2 FMA, fast MUFU gelu.
// ---------------------------------------------------------------------------

#define BSZ    32
#define LSEQ   1024
#define DIN    128
#define HDIM   256
#define NL     4
#define NMODE  32
#define DOUT   10
#define MROWS  (BSZ * LSEQ)          // 32768
#define HN     (HDIM * NMODE)        // 8192
#define NCH    16                    // time chunks
#define CHL    (LSEQ / NCH)          // 64 steps per chunk

// Scratch (device globals; no allocation allowed)
__device__ __align__(128) float g_h[MROWS * HDIM];
__device__ __align__(128) float g_y[MROWS * HDIM];
__device__ __align__(128) float g_z[MROWS * 2 * HDIM];
__device__ __align__(128) float g_coef[NL * 8 * HN];
__device__ __align__(128) float g_sre[BSZ * NCH * HN];
__device__ __align__(128) float g_sim[BSZ * NCH * HN];
__device__ __align__(16) __nv_bfloat16 g_wthi_enc[HDIM * DIN];
__device__ __align__(16) __nv_bfloat16 g_wtlo_enc[HDIM * DIN];
__device__ __align__(16) __nv_bfloat16 g_wthi[NL * 2 * HDIM * HDIM];
__device__ __align__(16) __nv_bfloat16 g_wtlo[NL * 2 * HDIM * HDIM];

typedef unsigned long long ull;

__device__ __forceinline__ ull pack2(float x) {
    ull r; asm("mov.b64 %0, {%1, %1};" : "=l"(r) : "f"(x)); return r;
}
__device__ __forceinline__ ull packf(float a, float b) {
    ull r; asm("mov.b64 %0, {%1, %2};" : "=l"(r) : "f"(a), "f"(b)); return r;
}
__device__ __forceinline__ ull fma2(ull a, ull b, ull c) {
    ull d; asm("fma.rn.f32x2 %0, %1, %2, %3;" : "=l"(d) : "l"(a), "l"(b), "l"(c)); return d;
}
union U2 { ull u; float2 f; };

__device__ __forceinline__ uint32_t smem_u32(const void* p) {
    uint32_t a;
    asm("{ .reg .u64 t; cvta.to.shared.u64 t, %1; cvt.u32.u64 %0, t; }"
        : "=r"(a) : "l"(p));
    return a;
}
__device__ __forceinline__ void ldsm4(uint32_t* r, uint32_t addr) {
    asm volatile("ldmatrix.sync.aligned.m8n8.x4.shared.b16 {%0,%1,%2,%3}, [%4];"
                 : "=r"(r[0]), "=r"(r[1]), "=r"(r[2]), "=r"(r[3]) : "r"(addr));
}
__device__ __forceinline__ void mma16816(float* c, const uint32_t* a, const uint32_t* b) {
    asm volatile("mma.sync.aligned.m16n8k16.row.col.f32.bf16.bf16.f32 "
                 "{%0,%1,%2,%3}, {%4,%5,%6,%7}, {%8,%9}, {%0,%1,%2,%3};"
                 : "+f"(c[0]), "+f"(c[1]), "+f"(c[2]), "+f"(c[3])
                 : "r"(a[0]), "r"(a[1]), "r"(a[2]), "r"(a[3]), "r"(b[0]), "r"(b[1]));
}
__device__ __forceinline__ uint32_t pkbf(float a, float b) {
    uint32_t ha = __bfloat16_as_ushort(__float2bfloat16_rn(a));
    uint32_t hb = __bfloat16_as_ushort(__float2bfloat16_rn(b));
    return ha | (hb << 16);
}

// gelu(x) = 0.5 x (1 + tanh(k(x + 0.044715 x^3))) = x * sigmoid(2k(x+0.044715x^3))
__device__ __forceinline__ float gelu_f(float x) {
    float t = fmaf(0.044715f * x * x, x, x);        // x + 0.044715 x^3
    return x / (1.0f + __expf(-1.5957691216057308f * t));
}

// ---------------------------------------------------------------------------
// Discretization prep.  Planes: 0 dAre, 1 dAim, 2 dBre, 3 dBim, 4 2Cre,
// 5 -2Cim, 6/7 = (dA^CHL) re/im.
// ---------------------------------------------------------------------------
__global__ void prep_coef(const float* __restrict__ log_dt,
                          const float* __restrict__ A_re_log,
                          const float* __restrict__ A_im,
                          const float* __restrict__ B_re,
                          const float* __restrict__ B_im,
                          const float* __restrict__ C_re,
                          const float* __restrict__ C_im)
{
    int t = blockIdx.x * 256 + threadIdx.x;
    if (t >= NL * HN) return;
    int l  = t / HN;
    int hn = t - l * HN;
    int hh = hn / NMODE;

    float Are = -expf(A_re_log[t]);
    float Aim = A_im[t];
    float dt  = expf(log_dt[l * HDIM + hh]);
    float dre = dt * Are, dim = dt * Aim;
    float e   = expf(dre);
    float dAre = e * cosf(dim);
    float dAim = e * sinf(dim);
    float nre = dAre - 1.0f, nim = dAim;
    float inv = 1.0f / (Are * Are + Aim * Aim);
    float qre = (nre * Are + nim * Aim) * inv;
    float qim = (nim * Are - nre * Aim) * inv;
    float bre = B_re[t], bim = B_im[t];
    float dBre = bre * qre - bim * qim;
    float dBim = bre * qim + bim * qre;

    float eL = expf((float)CHL * dre);
    float cL = cosf((float)CHL * dim);
    float sL = sinf((float)CHL * dim);

    float* cf = g_coef + (size_t)l * 8 * HN;
    cf[0 * HN + hn] = dAre;
    cf[1 * HN + hn] = dAim;
    cf[2 * HN + hn] = dBre;
    cf[3 * HN + hn] = dBim;
    cf[4 * HN + hn] =  2.0f * C_re[t];
    cf[5 * HN + hn] = -2.0f * C_im[t];
    cf[6 * HN + hn] = eL * cL;
    cf[7 * HN + hn] = eL * sL;
}

// ---------------------------------------------------------------------------
// Weight transpose + bf16 hi/lo split
// ---------------------------------------------------------------------------
__global__ void split_w(const float* __restrict__ W,
                        __nv_bfloat16* __restrict__ Whi,
                        __nv_bfloat16* __restrict__ Wlo, int K, int N)
{
    __shared__ float t[32][33];
    int n0 = blockIdx.x * 32, k0 = blockIdx.y * 32;
    const float* Wp = W + (size_t)blockIdx.z * K * N;
    __nv_bfloat16* Hp = Whi + (size_t)blockIdx.z * K * N;
    __nv_bfloat16* Lp = Wlo + (size_t)blockIdx.z * K * N;
#pragma unroll
    for (int yy = 0; yy < 32; yy += 8)
        t[threadIdx.y + yy][threadIdx.x] =
            Wp[(size_t)(k0 + threadIdx.y + yy) * N + n0 + threadIdx.x];
    __syncthreads();
#pragma unroll
    for (int yy = 0; yy < 32; yy += 8) {
        float v = t[threadIdx.x][threadIdx.y + yy];
        __nv_bfloat16 h = __float2bfloat16_rn(v);
        float r = v - __bfloat162float(h);
        size_t o = (size_t)(n0 + threadIdx.y + yy) * K + k0 + threadIdx.x;
        Hp[o] = h;
        Lp[o] = __float2bfloat16_rn(r);
    }
}

// ---------------------------------------------------------------------------
// bf16 split-3 tensor-core GEMM (2 CTAs/SM), fp32 A split in-kernel (R6)
// ---------------------------------------------------------------------------
template <int K>
__global__ __launch_bounds__(256, 2) void mma_gemm(
    const float* __restrict__ A,
    const __nv_bfloat16* __restrict__ Bhi,
    const __nv_bfloat16* __restrict__ Blo,
    const float* __restrict__ bias,
    float* __restrict__ C, int N)
{
    constexpr int KCH = K / 32;
    extern __shared__ char sm[];
    const uint32_t sbase = smem_u32(sm);

    const int tid  = threadIdx.x;
    const int warp = tid >> 5, lane = tid & 31;
    const int wm = warp >> 1, wn = warp & 1;
    const size_t m0 = (size_t)blockIdx.y * 128;
    const int    n0 = blockIdx.x * 128;

    float4 afr[2][2];
    uint4  bhfr[2], blfr[2];
    int usw[2];
#pragma unroll
    for (int i = 0; i < 2; i++) {
        int u = tid + i * 256;
        int row = u >> 2, c = u & 3;
        usw[i]  = row * 64 + ((c ^ ((row >> 1) & 3)) << 4);
    }

    auto ldg = [&](int cs) {
#pragma unroll
        for (int i = 0; i < 2; i++) {
            int u = tid + i * 256;
            int row = u >> 2, c = u & 3;
            const float4* pa = (const float4*)(A + (m0 + row) * K + cs * 32 + c * 8);
            afr[i][0] = pa[0];
            afr[i][1] = pa[1];
            bhfr[i] = *(const uint4*)(Bhi + (size_t)(n0 + row) * K + cs * 32 + c * 8);
            blfr[i] = *(const uint4*)(Blo + (size_t)(n0 + row) * K + cs * 32 + c * 8);
        }
    };
    auto sts = [&](int buf) {
        char* st = sm + buf * 32768;
#pragma unroll
        for (int i = 0; i < 2; i++) {
            float f[8] = {afr[i][0].x, afr[i][0].y, afr[i][0].z, afr[i][0].w,
                          afr[i][1].x, afr[i][1].y, afr[i][1].z, afr[i][1].w};
            uint32_t hw[4], lw[4];
#pragma unroll
            for (int j = 0; j < 4; j++) {
                float a = f[2 * j], b = f[2 * j + 1];
                __nv_bfloat16 ha = __float2bfloat16_rn(a);
                __nv_bfloat16 hb = __float2bfloat16_rn(b);
                hw[j] = (uint32_t)__bfloat16_as_ushort(ha) |
                        ((uint32_t)__bfloat16_as_ushort(hb) << 16);
                lw[j] = pkbf(a - __bfloat162float(ha), b - __bfloat162float(hb));
            }
            *(uint4*)(st + usw[i])         = make_uint4(hw[0], hw[1], hw[2], hw[3]);
            *(uint4*)(st + 8192 + usw[i])  = make_uint4(lw[0], lw[1], lw[2], lw[3]);
            *(uint4*)(st + 16384 + usw[i]) = bhfr[i];
            *(uint4*)(st + 24576 + usw[i]) = blfr[i];
        }
    };

    float acc[2][8][4];
#pragma unroll
    for (int a = 0; a < 2; a++)
#pragma unroll
        for (int b = 0; b < 8; b++)
#pragma unroll
            for (int c = 0; c < 4; c++) acc[a][b][c] = 0.f;

    auto compute = [&](int buf) {
        uint32_t ab = sbase + buf * 32768;
#pragma unroll
        for (int ks = 0; ks < 2; ks++) {
            uint32_t ah[2][4], al[2][4], bh[8][2], bl[8][2];
#pragma unroll
            for (int mt = 0; mt < 2; mt++) {
                int r  = wm * 32 + mt * 16 + (lane & 15);
                int ch = ks * 2 + (lane >> 4);
                uint32_t addr = ab + r * 64 + ((ch ^ ((r >> 1) & 3)) << 4);
                ldsm4(ah[mt], addr);
                ldsm4(al[mt], addr + 8192);
            }
#pragma unroll
            for (int j = 0; j < 4; j++) {
                int r  = wn * 64 + j * 16 + (lane & 15);
                int ch = ks * 2 + (lane >> 4);
                uint32_t addr = ab + 16384 + r * 64 + ((ch ^ ((r >> 1) & 3)) << 4);
                uint32_t q[4];
                ldsm4(q, addr);
                bh[2 * j][0] = q[0]; bh[2 * j + 1][0] = q[1];
                bh[2 * j][1] = q[2]; bh[2 * j + 1][1] = q[3];
                ldsm4(q, addr + 8192);
                bl[2 * j][0] = q[0]; bl[2 * j + 1][0] = q[1];
                bl[2 * j][1] = q[2]; bl[2 * j + 1][1] = q[3];
            }
#pragma unroll
            for (int mt = 0; mt < 2; mt++)
#pragma unroll
                for (int nt = 0; nt < 8; nt++) {
                    mma16816(acc[mt][nt], ah[mt], bh[nt]);
                    mma16816(acc[mt][nt], al[mt], bh[nt]);
                    mma16816(acc[mt][nt], ah[mt], bl[nt]);
                }
        }
    };

    ldg(0);
    sts(0);
    __syncthreads();
    for (int c = 0; c < KCH; c++) {
        if (c + 1 < KCH) ldg(c + 1);
        compute(c & 1);
        if (c + 1 < KCH) sts((c + 1) & 1);
        __syncthreads();
    }

#pragma unroll
    for (int mt = 0; mt < 2; mt++) {
#pragma unroll
        for (int nt = 0; nt < 8; nt++) {
            int r = (int)m0 + wm * 32 + mt * 16 + (lane >> 2);
            int n = n0 + wn * 64 + nt * 8 + (lane & 3) * 2;
            float b0 = bias[n], b1 = bias[n + 1];
            *(float2*)(C + (size_t)r * N + n) =
                make_float2(acc[mt][nt][0] + b0, acc[mt][nt][1] + b1);
            *(float2*)(C + (size_t)(r + 8) * N + n) =
                make_float2(acc[mt][nt][2] + b0, acc[mt][nt][3] + b1);
        }
    }
}

// ---------------------------------------------------------------------------
// Scan lane mapping: block = 128 thr owns (batch, 32 chans, one time chunk).
// 4 lanes per channel, 8 modes per lane (4 packed pairs).
// ---------------------------------------------------------------------------
#define SCAN_COEF_LOAD(NP)                                                    \
    ull dAre2[NP], dAim2[NP], ndAim2[NP], dBre2[NP], dBim2[NP];               \
    _Pragma("unroll")                                                         \
    for (int p = 0; p < NP; p++) {                                            \
        int c0 = hh * NMODE + mg + 2 * p;                                     \
        dAre2[p]  = packf(cf[0 * HN + c0], cf[0 * HN + c0 + 1]);              \
        dAim2[p]  = packf(cf[1 * HN + c0], cf[1 * HN + c0 + 1]);              \
        ndAim2[p] = packf(-cf[1 * HN + c0], -cf[1 * HN + c0 + 1]);            \
        dBre2[p]  = packf(cf[2 * HN + c0], cf[2 * HN + c0 + 1]);              \
        dBim2[p]  = packf(cf[3 * HN + c0], cf[3 * HN + c0 + 1]);              \
    }

// Phase A: local end-state per chunk (zero init), chunks 0..NCH-2
__global__ __launch_bounds__(128) void s4_state(
    const float* __restrict__ u, const float* __restrict__ cf)
{
    const int b     = blockIdx.y;
    const int chunk = blockIdx.z;
    const int h0    = blockIdx.x * 32;
    const int tid   = threadIdx.x;
    const int w     = tid >> 5;
    const int lane  = tid & 31;
    const int hcol  = (w << 3) + (lane >> 2);
    const int mg    = (lane & 3) * 8;
    const int hh    = h0 + hcol;

    SCAN_COEF_LOAD(4)

    __shared__ float su[CHL * 32];
    ull sre2[4] = {0ull, 0ull, 0ull, 0ull};
    ull sim2[4] = {0ull, 0ull, 0ull, 0ull};

    const float* ub = u + ((size_t)b * LSEQ + (size_t)chunk * CHL) * HDIM + h0;

#pragma unroll
    for (int k = 0; k < CHL * 32 / 128; k++) {
        int e = tid + k * 128;
        su[e] = ub[(size_t)(e >> 5) * HDIM + (e & 31)];
    }
    __syncthreads();
#pragma unroll 4
    for (int i = 0; i < CHL; i++) {
        ull uu2 = pack2(su[i * 32 + hcol]);
#pragma unroll
        for (int p = 0; p < 4; p++) {
            ull mre = fma2(dBre2[p], uu2, 0ull);
            ull mim = fma2(dBim2[p], uu2, 0ull);
            ull nre = fma2(ndAim2[p], sim2[p], mre);
            nre     = fma2(dAre2[p],  sre2[p], nre);
            ull nim = fma2(dAim2[p],  sre2[p], mim);
            nim     = fma2(dAre2[p],  sim2[p], nim);
            sre2[p] = nre; sim2[p] = nim;
        }
    }
    size_t sidx = ((size_t)b * NCH + chunk) * HN + hh * NMODE + mg;
#pragma unroll
    for (int p = 0; p < 4; p++) {
        U2 r, q; r.u = sre2[p]; q.u = sim2[p];
        g_sre[sidx + 2 * p]     = r.f.x;
        g_sre[sidx + 2 * p + 1] = r.f.y;
        g_sim[sidx + 2 * p]     = q.f.x;
        g_sim[sidx + 2 * p + 1] = q.f.y;
    }
}

// Phase B: cross-chunk scan (in place): end-states -> init states
__global__ __launch_bounds__(256) void s4_fix(const float* __restrict__ cf)
{
    int t = blockIdx.x * 256 + threadIdx.x;
    if (t >= BSZ * HN) return;
    int b  = t / HN;
    int hn = t - b * HN;
    float pre = cf[6 * HN + hn], pim = cf[7 * HN + hn];
    float Sre = 0.f, Sim = 0.f;
#pragma unroll
    for (int c = 0; c < NCH; c++) {
        size_t idx = ((size_t)b * NCH + c) * HN + hn;
        float ere = 0.f, eim = 0.f;
        if (c < NCH - 1) { ere = g_sre[idx]; eim = g_sim[idx]; }
        g_sre[idx] = Sre;
        g_sim[idx] = Sim;
        float nr = fmaf(pre, Sre, fmaf(-pim, Sim, ere));
        float ni = fmaf(pre, Sim, fmaf(pim, Sre, eim));
        Sre = nr; Sim = ni;
    }
}

// Phase C: full per-chunk scan with init state -> gelu(y + D*u) in fp32
__global__ __launch_bounds__(128) void s4_scan_out(
    const float* __restrict__ u, float* __restrict__ y,
    const float* __restrict__ cf, const float* __restrict__ Dv)
{
    const int b     = blockIdx.y;
    const int chunk = blockIdx.z;
    const int h0    = blockIdx.x * 32;
    const int tid   = threadIdx.x;
    const int w     = tid >> 5;
    const int lane  = tid & 31;
    const int hcol  = (w << 3) + (lane >> 2);
    const int mg    = (lane & 3) * 8;
    const int hh    = h0 + hcol;

    SCAN_COEF_LOAD(4)
    ull c2re2[4], c2in2[4];
#pragma unroll
    for (int p = 0; p < 4; p++) {
        int c0 = hh * NMODE + mg + 2 * p;
        c2re2[p] = packf(cf[4 * HN + c0], cf[4 * HN + c0 + 1]);
        c2in2[p] = packf(cf[5 * HN + c0], cf[5 * HN + c0 + 1]);
    }

    __shared__ float su[CHL * 32];
    __shared__ float sy[CHL * 32];
    __shared__ float sD[32];
    if (tid < 32) sD[tid] = Dv[h0 + tid];

    ull sre2[4], sim2[4];
    {
        size_t sidx = ((size_t)b * NCH + chunk) * HN + hh * NMODE + mg;
#pragma unroll
        for (int p = 0; p < 4; p++) {
            sre2[p] = packf(g_sre[sidx + 2 * p], g_sre[sidx + 2 * p + 1]);
            sim2[p] = packf(g_sim[sidx + 2 * p], g_sim[sidx + 2 * p + 1]);
        }
    }

    const size_t rbase = ((size_t)b * LSEQ + (size_t)chunk * CHL) * HDIM + h0;
    const float* ub = u + rbase;
    float*       yb = y + rbase;

#pragma unroll
    for (int k = 0; k < CHL * 32 / 128; k++) {
        int e = tid + k * 128;
        su[e] = ub[(size_t)(e >> 5) * HDIM + (e & 31)];
    }
    __syncthreads();
#pragma unroll 2
    for (int i = 0; i < CHL; i++) {
        ull uu2  = pack2(su[i * 32 + hcol]);
        ull cacc = 0ull;
#pragma unroll
        for (int p = 0; p < 4; p++) {
            ull mre = fma2(dBre2[p], uu2, 0ull);
            ull mim = fma2(dBim2[p], uu2, 0ull);
            ull nre = fma2(ndAim2[p], sim2[p], mre);
            nre     = fma2(dAre2[p],  sre2[p], nre);
            ull nim = fma2(dAim2[p],  sre2[p], mim);
            nim     = fma2(dAre2[p],  sim2[p], nim);
            sre2[p] = nre; sim2[p] = nim;
            cacc = fma2(c2re2[p], nre, cacc);
            cacc = fma2(c2in2[p], nim, cacc);
        }
        U2 cu; cu.u = cacc;
        float c = cu.f.x + cu.f.y;
        c += __shfl_xor_sync(0xffffffffu, c, 1);
        c += __shfl_xor_sync(0xffffffffu, c, 2);
        if ((lane & 3) == 0) sy[i * 32 + hcol] = c;
    }
    __syncthreads();
#pragma unroll
    for (int k = 0; k < CHL * 32 / 128; k++) {
        int e = tid + k * 128;
        float t = sy[e] + sD[e & 31] * su[e];
        yb[(size_t)(e >> 5) * HDIM + (e & 31)] = gelu_f(t);
    }
}

// ---------------------------------------------------------------------------
// GLU + residual + LayerNorm (in-place on h).  Warp per row of 256.
// ---------------------------------------------------------------------------
__global__ __launch_bounds__(256) void glu_res_ln(
    const float* __restrict__ z, float* __restrict__ h,
    const float* __restrict__ lnw, const float* __restrict__ lnb)
{
    const int row  = blockIdx.x * 8 + (threadIdx.x >> 5);
    const int lane = threadIdx.x & 31;
    const float* zr = z + (size_t)row * (2 * HDIM);
    float*       hr = h + (size_t)row * HDIM;

    float tv[8];
    float s = 0.f, s2 = 0.f;
#pragma unroll
    for (int k = 0; k < 8; k++) {
        int c = lane + k * 32;
        float a  = zr[c];
        float gg = zr[HDIM + c];
        float t  = a / (1.0f + __expf(-gg)) + hr[c];
        tv[k] = t;
        s  += t;
        s2  = fmaf(t, t, s2);
    }
#pragma unroll
    for (int o = 16; o; o >>= 1) {
        s  += __shfl_xor_sync(0xffffffffu, s,  o);
        s2 += __shfl_xor_sync(0xffffffffu, s2, o);
    }
    float mean = s * (1.0f / 256.0f);
    float var  = fmaf(-mean, mean, s2 * (1.0f / 256.0f));
    float rs   = rsqrtf(var + 1e-5f);
#pragma unroll
    for (int k = 0; k < 8; k++) {
        int c = lane + k * 32;
        hr[c] = fmaf((tv[k] - mean) * rs, lnw[c], lnb[c]);
    }
}

// ---------------------------------------------------------------------------
// Decoder: out[M,10] = h[M,256] @ dec_w[256,10] + dec_b
// ---------------------------------------------------------------------------
__global__ __launch_bounds__(256) void decoder(
    const float* __restrict__ h, const float* __restrict__ wv,
    const float* __restrict__ bvec, float* __restrict__ out)
{
    __shared__ float sw[HDIM * DOUT];
    for (int i = threadIdx.x; i < HDIM * DOUT; i += 256) sw[i] = wv[i];
    __syncthreads();
    int o = blockIdx.x * 256 + threadIdx.x;
    int r = o / DOUT, n = o - r * DOUT;
    const float* hr = h + (size_t)r * HDIM;
    float s = bvec[n];
#pragma unroll 8
    for (int k = 0; k < HDIM; k++) s = fmaf(hr[k], sw[k * DOUT + n], s);
    out[o] = s;
}

// ---------------------------------------------------------------------------
extern "C" void kernel_launch(void* const* d_in, const int* in_sizes, int n_in,
                              void* d_out, int out_size)
{
    const float* x        = (const float*)d_in[0];
    const float* enc_w    = (const float*)d_in[1];
    const float* enc_b    = (const float*)d_in[2];
    const float* log_dt   = (const float*)d_in[3];
    const float* A_re_log = (const float*)d_in[4];
    const float* A_im     = (const float*)d_in[5];
    const float* B_re     = (const float*)d_in[6];
    const float* B_im     = (const float*)d_in[7];
    const float* C_re     = (const float*)d_in[8];
    const float* C_im     = (const float*)d_in[9];
    const float* Dp       = (const float*)d_in[10];
    const float* ln_w     = (const float*)d_in[11];
    const float* ln_b     = (const float*)d_in[12];
    const float* out_w    = (const float*)d_in[13];
    const float* out_b    = (const float*)d_in[14];
    const float* dec_w    = (const float*)d_in[15];
    const float* dec_b    = (const float*)d_in[16];
    float* outp = (float*)d_out;

    float *ph, *py, *pz, *pcf;
    __nv_bfloat16 *pwhE, *pwlE, *pwh, *pwl;
    cudaGetSymbolAddress((void**)&ph,  g_h);
    cudaGetSymbolAddress((void**)&py,  g_y);
    cudaGetSymbolAddress((void**)&pz,  g_z);
    cudaGetSymbolAddress((void**)&pcf, g_coef);
    cudaGetSymbolAddress((void**)&pwhE, g_wthi_enc);
    cudaGetSymbolAddress((void**)&pwlE, g_wtlo_enc);
    cudaGetSymbolAddress((void**)&pwh, g_wthi);
    cudaGetSymbolAddress((void**)&pwl, g_wtlo);

    cudaFuncSetAttribute(mma_gemm<128>,
                         cudaFuncAttributeMaxDynamicSharedMemorySize, 65536);
    cudaFuncSetAttribute(mma_gemm<256>,
                         cudaFuncAttributeMaxDynamicSharedMemorySize, 65536);

    prep_coef<<<(NL * HN + 255) / 256, 256>>>(log_dt, A_re_log, A_im,
                                              B_re, B_im, C_re, C_im);
    split_w<<<dim3(HDIM / 32, DIN / 32, 1), dim3(32, 8)>>>(enc_w, pwhE, pwlE,
                                                           DIN, HDIM);
    split_w<<<dim3(2 * HDIM / 32, HDIM / 32, NL), dim3(32, 8)>>>(out_w, pwh, pwl,
                                                                 HDIM, 2 * HDIM);

    // encoder: h = x @ enc_w + enc_b   (M=32768, N=256, K=128)
    mma_gemm<128><<<dim3(2, MROWS / 128), 256, 65536>>>(x, pwhE, pwlE, enc_b,
                                                        ph, HDIM);

    for (int l = 0; l < NL; l++) {
        const float* cfl = pcf + (size_t)l * 8 * HN;
        s4_state<<<dim3(HDIM / 32, BSZ, NCH - 1), 128>>>(ph, cfl);
        s4_fix<<<(BSZ * HN + 255) / 256, 256>>>(cfl);
        s4_scan_out<<<dim3(HDIM / 32, BSZ, NCH), 128>>>(ph, py, cfl,
                                                        Dp + l * HDIM);
        mma_gemm<256><<<dim3(4, MROWS / 128), 256, 65536>>>(
            py, pwh + (size_t)l * 2 * HDIM * HDIM,
            pwl + (size_t)l * 2 * HDIM * HDIM,
            out_b + l * 2 * HDIM, pz, 2 * HDIM);
        glu_res_ln<<<MROWS / 8, 256>>>(pz, ph, ln_w + l * HDIM, ln_b + l * HDIM);
    }

    decoder<<<(MROWS * DOUT) / 256, 256>>>(ph, dec_w, dec_b, outp);
}

// round 13
// speedup vs baseline: 1.1502x; 1.1292x over previous
#include <cuda_runtime.h>
#include <cuda_bf16.h>
#include <cstdint>

// ---------------------------------------------------------------------------
// S4D model forward:  encoder GEMM -> 4x( S4 scan+gelu -> GEMM -> GLU+res+LN )
//                     -> decoder
// GEMMs: mma.sync m16n8k16 bf16, 3-pass hi/lo split, 2 CTAs/SM,
//        A register-staged split, B planes via cp.async.
// Scan:  time-chunked (8 chunks) 3-phase linear-recurrence decomposition,
//        packed fp32x2 FMA (R6-proven mapping), MUFU activations.
// ---------------------------------------------------------------------------

#define BSZ    32
#define LSEQ   1024
#define DIN    128
#define HDIM   256
#define NL     4
#define NMODE  32
#define DOUT   10
#define MROWS  (BSZ * LSEQ)          // 32768
#define HN     (HDIM * NMODE)        // 8192
#define NCH    8                     // time chunks
#define CHL    (LSEQ / NCH)          // 128 steps per chunk

// Scratch (device globals; no allocation allowed)
__device__ __align__(128) float g_h[MROWS * HDIM];
__device__ __align__(128) float g_y[MROWS * HDIM];
__device__ __align__(128) float g_z[MROWS * 2 * HDIM];
__device__ __align__(128) float g_coef[NL * 8 * HN];
__device__ __align__(128) float g_sre[BSZ * NCH * HN];
__device__ __align__(128) float g_sim[BSZ * NCH * HN];
__device__ __align__(16) __nv_bfloat16 g_wthi_enc[HDIM * DIN];
__device__ __align__(16) __nv_bfloat16 g_wtlo_enc[HDIM * DIN];
__device__ __align__(16) __nv_bfloat16 g_wthi[NL * 2 * HDIM * HDIM];
__device__ __align__(16) __nv_bfloat16 g_wtlo[NL * 2 * HDIM * HDIM];

typedef unsigned long long ull;

__device__ __forceinline__ ull pack2(float x) {
    ull r; asm("mov.b64 %0, {%1, %1};" : "=l"(r) : "f"(x)); return r;
}
__device__ __forceinline__ ull packf(float a, float b) {
    ull r; asm("mov.b64 %0, {%1, %2};" : "=l"(r) : "f"(a), "f"(b)); return r;
}
__device__ __forceinline__ ull fma2(ull a, ull b, ull c) {
    ull d; asm("fma.rn.f32x2 %0, %1, %2, %3;" : "=l"(d) : "l"(a), "l"(b), "l"(c)); return d;
}
union U2 { ull u; float2 f; };

__device__ __forceinline__ uint32_t smem_u32(const void* p) {
    uint32_t a;
    asm("{ .reg .u64 t; cvta.to.shared.u64 t, %1; cvt.u32.u64 %0, t; }"
        : "=r"(a) : "l"(p));
    return a;
}
__device__ __forceinline__ void ldsm4(uint32_t* r, uint32_t addr) {
    asm volatile("ldmatrix.sync.aligned.m8n8.x4.shared.b16 {%0,%1,%2,%3}, [%4];"
                 : "=r"(r[0]), "=r"(r[1]), "=r"(r[2]), "=r"(r[3]) : "r"(addr));
}
__device__ __forceinline__ void mma16816(float* c, const uint32_t* a, const uint32_t* b) {
    asm volatile("mma.sync.aligned.m16n8k16.row.col.f32.bf16.bf16.f32 "
                 "{%0,%1,%2,%3}, {%4,%5,%6,%7}, {%8,%9}, {%0,%1,%2,%3};"
                 : "+f"(c[0]), "+f"(c[1]), "+f"(c[2]), "+f"(c[3])
                 : "r"(a[0]), "r"(a[1]), "r"(a[2]), "r"(a[3]), "r"(b[0]), "r"(b[1]));
}
__device__ __forceinline__ void cpasync16(uint32_t d, const void* s) {
    asm volatile("cp.async.cg.shared.global [%0], [%1], 16;" :: "r"(d), "l"(s));
}
__device__ __forceinline__ uint32_t pkbf(float a, float b) {
    uint32_t ha = __bfloat16_as_ushort(__float2bfloat16_rn(a));
    uint32_t hb = __bfloat16_as_ushort(__float2bfloat16_rn(b));
    return ha | (hb << 16);
}

// gelu(x) = x * sigmoid(1.5957691*(x + 0.044715 x^3)), MUFU exp + fast div
__device__ __forceinline__ float gelu_f(float x) {
    float t = fmaf(0.044715f * x * x, x, x);
    return __fdividef(x, 1.0f + __expf(-1.5957691216057308f * t));
}

// ---------------------------------------------------------------------------
// Discretization prep.  Planes: 0 dAre, 1 dAim, 2 dBre, 3 dBim, 4 2Cre,
// 5 -2Cim, 6/7 = (dA^CHL) re/im.
// ---------------------------------------------------------------------------
__global__ void prep_coef(const float* __restrict__ log_dt,
                          const float* __restrict__ A_re_log,
                          const float* __restrict__ A_im,
                          const float* __restrict__ B_re,
                          const float* __restrict__ B_im,
                          const float* __restrict__ C_re,
                          const float* __restrict__ C_im)
{
    int t = blockIdx.x * 256 + threadIdx.x;
    if (t >= NL * HN) return;
    int l  = t / HN;
    int hn = t - l * HN;
    int hh = hn / NMODE;

    float Are = -expf(A_re_log[t]);
    float Aim = A_im[t];
    float dt  = expf(log_dt[l * HDIM + hh]);
    float dre = dt * Are, dim = dt * Aim;
    float e   = expf(dre);
    float dAre = e * cosf(dim);
    float dAim = e * sinf(dim);
    float nre = dAre - 1.0f, nim = dAim;
    float inv = 1.0f / (Are * Are + Aim * Aim);
    float qre = (nre * Are + nim * Aim) * inv;
    float qim = (nim * Are - nre * Aim) * inv;
    float bre = B_re[t], bim = B_im[t];
    float dBre = bre * qre - bim * qim;
    float dBim = bre * qim + bim * qre;

    float eL = expf((float)CHL * dre);
    float cL = cosf((float)CHL * dim);
    float sL = sinf((float)CHL * dim);

    float* cf = g_coef + (size_t)l * 8 * HN;
    cf[0 * HN + hn] = dAre;
    cf[1 * HN + hn] = dAim;
    cf[2 * HN + hn] = dBre;
    cf[3 * HN + hn] = dBim;
    cf[4 * HN + hn] =  2.0f * C_re[t];
    cf[5 * HN + hn] = -2.0f * C_im[t];
    cf[6 * HN + hn] = eL * cL;
    cf[7 * HN + hn] = eL * sL;
}

// ---------------------------------------------------------------------------
// Weight transpose + bf16 hi/lo split
// ---------------------------------------------------------------------------
__global__ void split_w(const float* __restrict__ W,
                        __nv_bfloat16* __restrict__ Whi,
                        __nv_bfloat16* __restrict__ Wlo, int K, int N)
{
    __shared__ float t[32][33];
    int n0 = blockIdx.x * 32, k0 = blockIdx.y * 32;
    const float* Wp = W + (size_t)blockIdx.z * K * N;
    __nv_bfloat16* Hp = Whi + (size_t)blockIdx.z * K * N;
    __nv_bfloat16* Lp = Wlo + (size_t)blockIdx.z * K * N;
#pragma unroll
    for (int yy = 0; yy < 32; yy += 8)
        t[threadIdx.y + yy][threadIdx.x] =
            Wp[(size_t)(k0 + threadIdx.y + yy) * N + n0 + threadIdx.x];
    __syncthreads();
#pragma unroll
    for (int yy = 0; yy < 32; yy += 8) {
        float v = t[threadIdx.x][threadIdx.y + yy];
        __nv_bfloat16 h = __float2bfloat16_rn(v);
        float r = v - __bfloat162float(h);
        size_t o = (size_t)(n0 + threadIdx.y + yy) * K + k0 + threadIdx.x;
        Hp[o] = h;
        Lp[o] = __float2bfloat16_rn(r);
    }
}

// ---------------------------------------------------------------------------
// bf16 split-3 tensor-core GEMM (2 CTAs/SM).
// A fp32 -> register-staged hi/lo split + STS; B planes via cp.async.
// Stage (32KB): [Ahi 8K][Alo 8K][Bhi 8K][Blo 8K], double buffered.
// ---------------------------------------------------------------------------
template <int K>
__global__ __launch_bounds__(256, 2) void mma_gemm(
    const float* __restrict__ A,
    const __nv_bfloat16* __restrict__ Bhi,
    const __nv_bfloat16* __restrict__ Blo,
    const float* __restrict__ bias,
    float* __restrict__ C, int N)
{
    constexpr int KCH = K / 32;
    extern __shared__ char sm[];
    const uint32_t sbase = smem_u32(sm);

    const int tid  = threadIdx.x;
    const int warp = tid >> 5, lane = tid & 31;
    const int wm = warp >> 1, wn = warp & 1;
    const size_t m0 = (size_t)blockIdx.y * 128;
    const int    n0 = blockIdx.x * 128;

    // per-thread copy units: u = tid + i*256, row = u>>2 (0..127), c = u&3
    float4 afr[2][2];
    int usw[2];
#pragma unroll
    for (int i = 0; i < 2; i++) {
        int u = tid + i * 256;
        int row = u >> 2, c = u & 3;
        usw[i]  = row * 64 + ((c ^ ((row >> 1) & 3)) << 4);
    }

    auto ldgA = [&](int cs) {
#pragma unroll
        for (int i = 0; i < 2; i++) {
            int u = tid + i * 256;
            int row = u >> 2, c = u & 3;
            const float4* pa = (const float4*)(A + (m0 + row) * K + cs * 32 + c * 8);
            afr[i][0] = pa[0];
            afr[i][1] = pa[1];
        }
    };
    auto stsA = [&](int buf) {
        char* st = sm + buf * 32768;
#pragma unroll
        for (int i = 0; i < 2; i++) {
            float f[8] = {afr[i][0].x, afr[i][0].y, afr[i][0].z, afr[i][0].w,
                          afr[i][1].x, afr[i][1].y, afr[i][1].z, afr[i][1].w};
            uint32_t hw[4], lw[4];
#pragma unroll
            for (int j = 0; j < 4; j++) {
                float a = f[2 * j], b = f[2 * j + 1];
                __nv_bfloat16 ha = __float2bfloat16_rn(a);
                __nv_bfloat16 hb = __float2bfloat16_rn(b);
                hw[j] = (uint32_t)__bfloat16_as_ushort(ha) |
                        ((uint32_t)__bfloat16_as_ushort(hb) << 16);
                lw[j] = pkbf(a - __bfloat162float(ha), b - __bfloat162float(hb));
            }
            *(uint4*)(st + usw[i])        = make_uint4(hw[0], hw[1], hw[2], hw[3]);
            *(uint4*)(st + 8192 + usw[i]) = make_uint4(lw[0], lw[1], lw[2], lw[3]);
        }
    };
    auto cpB = [&](int cs, int buf) {
        uint32_t st = sbase + buf * 32768 + 16384;
#pragma unroll
        for (int i = 0; i < 2; i++) {
            int u = tid + i * 256;
            int row = u >> 2, c = u & 3;
            uint32_t d = st + usw[i];
            const __nv_bfloat16* sh = Bhi + (size_t)(n0 + row) * K + cs * 32 + c * 8;
            const __nv_bfloat16* sl = Blo + (size_t)(n0 + row) * K + cs * 32 + c * 8;
            cpasync16(d, sh);
            cpasync16(d + 8192, sl);
        }
        asm volatile("cp.async.commit_group;");
    };

    float acc[2][8][4];
#pragma unroll
    for (int a = 0; a < 2; a++)
#pragma unroll
        for (int b = 0; b < 8; b++)
#pragma unroll
            for (int c = 0; c < 4; c++) acc[a][b][c] = 0.f;

    auto compute = [&](int buf) {
        uint32_t ab = sbase + buf * 32768;
#pragma unroll
        for (int ks = 0; ks < 2; ks++) {
            uint32_t ah[2][4], al[2][4], bh[8][2], bl[8][2];
#pragma unroll
            for (int mt = 0; mt < 2; mt++) {
                int r  = wm * 32 + mt * 16 + (lane & 15);
                int ch = ks * 2 + (lane >> 4);
                uint32_t addr = ab + r * 64 + ((ch ^ ((r >> 1) & 3)) << 4);
                ldsm4(ah[mt], addr);
                ldsm4(al[mt], addr + 8192);
            }
#pragma unroll
            for (int j = 0; j < 4; j++) {
                int r  = wn * 64 + j * 16 + (lane & 15);
                int ch = ks * 2 + (lane >> 4);
                uint32_t addr = ab + 16384 + r * 64 + ((ch ^ ((r >> 1) & 3)) << 4);
                uint32_t q[4];
                ldsm4(q, addr);
                bh[2 * j][0] = q[0]; bh[2 * j + 1][0] = q[1];
                bh[2 * j][1] = q[2]; bh[2 * j + 1][1] = q[3];
                ldsm4(q, addr + 8192);
                bl[2 * j][0] = q[0]; bl[2 * j + 1][0] = q[1];
                bl[2 * j][1] = q[2]; bl[2 * j + 1][1] = q[3];
            }
#pragma unroll
            for (int mt = 0; mt < 2; mt++)
#pragma unroll
                for (int nt = 0; nt < 8; nt++) {
                    mma16816(acc[mt][nt], ah[mt], bh[nt]);
                    mma16816(acc[mt][nt], al[mt], bh[nt]);
                    mma16816(acc[mt][nt], ah[mt], bl[nt]);
                }
        }
    };

    // prologue: fill buffer 0
    ldgA(0);
    cpB(0, 0);
    stsA(0);
    if (KCH > 1) ldgA(1);
    asm volatile("cp.async.wait_group 0;" ::: "memory");
    __syncthreads();

    for (int c = 0; c < KCH; c++) {
        // buf (c+1)&1 was released by the sync at end of previous iteration
        if (c + 1 < KCH) cpB(c + 1, (c + 1) & 1);
        compute(c & 1);
        if (c + 1 < KCH) {
            stsA((c + 1) & 1);
            if (c + 2 < KCH) ldgA(c + 2);
            asm volatile("cp.async.wait_group 0;" ::: "memory");
        }
        __syncthreads();
    }

#pragma unroll
    for (int mt = 0; mt < 2; mt++) {
#pragma unroll
        for (int nt = 0; nt < 8; nt++) {
            int r = (int)m0 + wm * 32 + mt * 16 + (lane >> 2);
            int n = n0 + wn * 64 + nt * 8 + (lane & 3) * 2;
            float b0 = bias[n], b1 = bias[n + 1];
            *(float2*)(C + (size_t)r * N + n) =
                make_float2(acc[mt][nt][0] + b0, acc[mt][nt][1] + b1);
            *(float2*)(C + (size_t)(r + 8) * N + n) =
                make_float2(acc[mt][nt][2] + b0, acc[mt][nt][3] + b1);
        }
    }
}

// ---------------------------------------------------------------------------
// Scan lane mapping: block = 128 thr owns (batch, 32 chans, one time chunk).
// 4 lanes per channel, 8 modes per lane (4 packed pairs).
// ---------------------------------------------------------------------------
#define SCAN_COEF_LOAD(NP)                                                    \
    ull dAre2[NP], dAim2[NP], ndAim2[NP], dBre2[NP], dBim2[NP];               \
    _Pragma("unroll")                                                         \
    for (int p = 0; p < NP; p++) {                                            \
        int c0 = hh * NMODE + mg + 2 * p;                                     \
        dAre2[p]  = packf(cf[0 * HN + c0], cf[0 * HN + c0 + 1]);              \
        dAim2[p]  = packf(cf[1 * HN + c0], cf[1 * HN + c0 + 1]);              \
        ndAim2[p] = packf(-cf[1 * HN + c0], -cf[1 * HN + c0 + 1]);            \
        dBre2[p]  = packf(cf[2 * HN + c0], cf[2 * HN + c0 + 1]);              \
        dBim2[p]  = packf(cf[3 * HN + c0], cf[3 * HN + c0 + 1]);              \
    }

// Phase A: local end-state per chunk (zero init), chunks 0..NCH-2
__global__ __launch_bounds__(128) void s4_state(
    const float* __restrict__ u, const float* __restrict__ cf)
{
    const int b     = blockIdx.y;
    const int chunk = blockIdx.z;
    const int h0    = blockIdx.x * 32;
    const int tid   = threadIdx.x;
    const int w     = tid >> 5;
    const int lane  = tid & 31;
    const int hcol  = (w << 3) + (lane >> 2);
    const int mg    = (lane & 3) * 8;
    const int hh    = h0 + hcol;

    SCAN_COEF_LOAD(4)

    __shared__ float su[64 * 32];
    ull sre2[4] = {0ull, 0ull, 0ull, 0ull};
    ull sim2[4] = {0ull, 0ull, 0ull, 0ull};

    const float* ub = u + ((size_t)b * LSEQ + (size_t)chunk * CHL) * HDIM + h0;

    for (int l0 = 0; l0 < CHL; l0 += 64) {
        __syncthreads();
#pragma unroll
        for (int k = 0; k < 16; k++) {
            int e = tid + k * 128;
            su[e] = ub[(size_t)(l0 + (e >> 5)) * HDIM + (e & 31)];
        }
        __syncthreads();
#pragma unroll 4
        for (int i = 0; i < 64; i++) {
            ull uu2 = pack2(su[i * 32 + hcol]);
#pragma unroll
            for (int p = 0; p < 4; p++) {
                ull mre = fma2(dBre2[p], uu2, 0ull);
                ull mim = fma2(dBim2[p], uu2, 0ull);
                ull nre = fma2(ndAim2[p], sim2[p], mre);
                nre     = fma2(dAre2[p],  sre2[p], nre);
                ull nim = fma2(dAim2[p],  sre2[p], mim);
                nim     = fma2(dAre2[p],  sim2[p], nim);
                sre2[p] = nre; sim2[p] = nim;
            }
        }
    }
    size_t sidx = ((size_t)b * NCH + chunk) * HN + hh * NMODE + mg;
#pragma unroll
    for (int p = 0; p < 4; p++) {
        U2 r, q; r.u = sre2[p]; q.u = sim2[p];
        g_sre[sidx + 2 * p]     = r.f.x;
        g_sre[sidx + 2 * p + 1] = r.f.y;
        g_sim[sidx + 2 * p]     = q.f.x;
        g_sim[sidx + 2 * p + 1] = q.f.y;
    }
}

// Phase B: cross-chunk scan (in place): end-states -> init states
__global__ __launch_bounds__(256) void s4_fix(const float* __restrict__ cf)
{
    int t = blockIdx.x * 256 + threadIdx.x;
    if (t >= BSZ * HN) return;
    int b  = t / HN;
    int hn = t - b * HN;
    float pre = cf[6 * HN + hn], pim = cf[7 * HN + hn];
    float Sre = 0.f, Sim = 0.f;
#pragma unroll
    for (int c = 0; c < NCH; c++) {
        size_t idx = ((size_t)b * NCH + c) * HN + hn;
        float ere = 0.f, eim = 0.f;
        if (c < NCH - 1) { ere = g_sre[idx]; eim = g_sim[idx]; }
        g_sre[idx] = Sre;
        g_sim[idx] = Sim;
        float nr = fmaf(pre, Sre, fmaf(-pim, Sim, ere));
        float ni = fmaf(pre, Sim, fmaf(pim, Sre, eim));
        Sre = nr; Sim = ni;
    }
}

// Phase C: full per-chunk scan with init state -> gelu(y + D*u) in fp32
__global__ __launch_bounds__(128) void s4_scan_out(
    const float* __restrict__ u, float* __restrict__ y,
    const float* __restrict__ cf, const float* __restrict__ Dv)
{
    const int b     = blockIdx.y;
    const int chunk = blockIdx.z;
    const int h0    = blockIdx.x * 32;
    const int tid   = threadIdx.x;
    const int w     = tid >> 5;
    const int lane  = tid & 31;
    const int hcol  = (w << 3) + (lane >> 2);
    const int mg    = (lane & 3) * 8;
    const int hh    = h0 + hcol;

    SCAN_COEF_LOAD(4)
    ull c2re2[4], c2in2[4];
#pragma unroll
    for (int p = 0; p < 4; p++) {
        int c0 = hh * NMODE + mg + 2 * p;
        c2re2[p] = packf(cf[4 * HN + c0], cf[4 * HN + c0 + 1]);
        c2in2[p] = packf(cf[5 * HN + c0], cf[5 * HN + c0 + 1]);
    }

    __shared__ float su[64 * 32];
    __shared__ float sy[64 * 32];
    __shared__ float sD[32];
    if (tid < 32) sD[tid] = Dv[h0 + tid];

    ull sre2[4], sim2[4];
    {
        size_t sidx = ((size_t)b * NCH + chunk) * HN + hh * NMODE + mg;
#pragma unroll
        for (int p = 0; p < 4; p++) {
            sre2[p] = packf(g_sre[sidx + 2 * p], g_sre[sidx + 2 * p + 1]);
            sim2[p] = packf(g_sim[sidx + 2 * p], g_sim[sidx + 2 * p + 1]);
        }
    }

    const size_t rbase = ((size_t)b * LSEQ + (size_t)chunk * CHL) * HDIM + h0;
    const float* ub = u + rbase;
    float*       yb = y + rbase;

    for (int l0 = 0; l0 < CHL; l0 += 64) {
        __syncthreads();
#pragma unroll
        for (int k = 0; k < 16; k++) {
            int e = tid + k * 128;
            su[e] = ub[(size_t)(l0 + (e >> 5)) * HDIM + (e & 31)];
        }
        __syncthreads();
#pragma unroll 2
        for (int i = 0; i < 64; i++) {
            ull uu2  = pack2(su[i * 32 + hcol]);
            ull cacc = 0ull;
#pragma unroll
            for (int p = 0; p < 4; p++) {
                ull mre = fma2(dBre2[p], uu2, 0ull);
                ull mim = fma2(dBim2[p], uu2, 0ull);
                ull nre = fma2(ndAim2[p], sim2[p], mre);
                nre     = fma2(dAre2[p],  sre2[p], nre);
                ull nim = fma2(dAim2[p],  sre2[p], mim);
                nim     = fma2(dAre2[p],  sim2[p], nim);
                sre2[p] = nre; sim2[p] = nim;
                cacc = fma2(c2re2[p], nre, cacc);
                cacc = fma2(c2in2[p], nim, cacc);
            }
            U2 cu; cu.u = cacc;
            float c = cu.f.x + cu.f.y;
            c += __shfl_xor_sync(0xffffffffu, c, 1);
            c += __shfl_xor_sync(0xffffffffu, c, 2);
            if ((lane & 3) == 0) sy[i * 32 + hcol] = c;
        }
        __syncthreads();
#pragma unroll
        for (int k = 0; k < 16; k++) {
            int e = tid + k * 128;
            float t = sy[e] + sD[e & 31] * su[e];
            yb[(size_t)(l0 + (e >> 5)) * HDIM + (e & 31)] = gelu_f(t);
        }
    }
}

// ---------------------------------------------------------------------------
// GLU + residual + LayerNorm (in-place on h).  Warp per row of 256.
// ---------------------------------------------------------------------------
__global__ __launch_bounds__(256) void glu_res_ln(
    const float* __restrict__ z, float* __restrict__ h,
    const float* __restrict__ lnw, const float* __restrict__ lnb)
{
    const int row  = blockIdx.x * 8 + (threadIdx.x >> 5);
    const int lane = threadIdx.x & 31;
    const float* zr = z + (size_t)row * (2 * HDIM);
    float*       hr = h + (size_t)row * HDIM;

    float tv[8];
    float s = 0.f, s2 = 0.f;
#pragma unroll
    for (int k = 0; k < 8; k++) {
        int c = lane + k * 32;
        float a  = zr[c];
        float gg = zr[HDIM + c];
        float t  = __fdividef(a, 1.0f + __expf(-gg)) + hr[c];
        tv[k] = t;
        s  += t;
        s2  = fmaf(t, t, s2);
    }
#pragma unroll
    for (int o = 16; o; o >>= 1) {
        s  += __shfl_xor_sync(0xffffffffu, s,  o);
        s2 += __shfl_xor_sync(0xffffffffu, s2, o);
    }
    float mean = s * (1.0f / 256.0f);
    float var  = fmaf(-mean, mean, s2 * (1.0f / 256.0f));
    float rs   = rsqrtf(var + 1e-5f);
#pragma unroll
    for (int k = 0; k < 8; k++) {
        int c = lane + k * 32;
        hr[c] = fmaf((tv[k] - mean) * rs, lnw[c], lnb[c]);
    }
}

// ---------------------------------------------------------------------------
// Decoder: out[M,10] = h[M,256] @ dec_w[256,10] + dec_b
// ---------------------------------------------------------------------------
__global__ __launch_bounds__(256) void decoder(
    const float* __restrict__ h, const float* __restrict__ wv,
    const float* __restrict__ bvec, float* __restrict__ out)
{
    __shared__ float sw[HDIM * DOUT];
    for (int i = threadIdx.x; i < HDIM * DOUT; i += 256) sw[i] = wv[i];
    __syncthreads();
    int o = blockIdx.x * 256 + threadIdx.x;
    int r = o / DOUT, n = o - r * DOUT;
    const float* hr = h + (size_t)r * HDIM;
    float s = bvec[n];
#pragma unroll 8
    for (int k = 0; k < HDIM; k++) s = fmaf(hr[k], sw[k * DOUT + n], s);
    out[o] = s;
}

// ---------------------------------------------------------------------------
extern "C" void kernel_launch(void* const* d_in, const int* in_sizes, int n_in,
                              void* d_out, int out_size)
{
    const float* x        = (const float*)d_in[0];
    const float* enc_w    = (const float*)d_in[1];
    const float* enc_b    = (const float*)d_in[2];
    const float* log_dt   = (const float*)d_in[3];
    const float* A_re_log = (const float*)d_in[4];
    const float* A_im     = (const float*)d_in[5];
    const float* B_re     = (const float*)d_in[6];
    const float* B_im     = (const float*)d_in[7];
    const float* C_re     = (const float*)d_in[8];
    const float* C_im     = (const float*)d_in[9];
    const float* Dp       = (const float*)d_in[10];
    const float* ln_w     = (const float*)d_in[11];
    const float* ln_b     = (const float*)d_in[12];
    const float* out_w    = (const float*)d_in[13];
    const float* out_b    = (const float*)d_in[14];
    const float* dec_w    = (const float*)d_in[15];
    const float* dec_b    = (const float*)d_in[16];
    float* outp = (float*)d_out;

    float *ph, *py, *pz, *pcf;
    __nv_bfloat16 *pwhE, *pwlE, *pwh, *pwl;
    cudaGetSymbolAddress((void**)&ph,  g_h);
    cudaGetSymbolAddress((void**)&py,  g_y);
    cudaGetSymbolAddress((void**)&pz,  g_z);
    cudaGetSymbolAddress((void**)&pcf, g_coef);
    cudaGetSymbolAddress((void**)&pwhE, g_wthi_enc);
    cudaGetSymbolAddress((void**)&pwlE, g_wtlo_enc);
    cudaGetSymbolAddress((void**)&pwh, g_wthi);
    cudaGetSymbolAddress((void**)&pwl, g_wtlo);

    cudaFuncSetAttribute(mma_gemm<128>,
                         cudaFuncAttributeMaxDynamicSharedMemorySize, 65536);
    cudaFuncSetAttribute(mma_gemm<256>,
                         cudaFuncAttributeMaxDynamicSharedMemorySize, 65536);

    prep_coef<<<(NL * HN + 255) / 256, 256>>>(log_dt, A_re_log, A_im,
                                              B_re, B_im, C_re, C_im);
    split_w<<<dim3(HDIM / 32, DIN / 32, 1), dim3(32, 8)>>>(enc_w, pwhE, pwlE,
                                                           DIN, HDIM);
    split_w<<<dim3(2 * HDIM / 32, HDIM / 32, NL), dim3(32, 8)>>>(out_w, pwh, pwl,
                                                                 HDIM, 2 * HDIM);

    // encoder: h = x @ enc_w + enc_b   (M=32768, N=256, K=128)
    mma_gemm<128><<<dim3(2, MROWS / 128), 256, 65536>>>(x, pwhE, pwlE, enc_b,
                                                        ph, HDIM);

    for (int l = 0; l < NL; l++) {
        const float* cfl = pcf + (size_t)l * 8 * HN;
        s4_state<<<dim3(HDIM / 32, BSZ, NCH - 1), 128>>>(ph, cfl);
        s4_fix<<<(BSZ * HN + 255) / 256, 256>>>(cfl);
        s4_scan_out<<<dim3(HDIM / 32, BSZ, NCH), 128>>>(ph, py, cfl,
                                                        Dp + l * HDIM);
        mma_gemm<256><<<dim3(4, MROWS / 128), 256, 65536>>>(
            py, pwh + (size_t)l * 2 * HDIM * HDIM,
            pwl + (size_t)l * 2 * HDIM * HDIM,
            out_b + l * 2 * HDIM, pz, 2 * HDIM);
        glu_res_ln<<<MROWS / 8, 256>>>(pz, ph, ln_w + l * HDIM, ln_b + l * HDIM);
    }

    decoder<<<(MROWS * DOUT) / 256, 256>>>(ph, dec_w, dec_b, outp);
}

// round 15
// speedup vs baseline: 1.2255x; 1.0654x over previous
#include <cuda_runtime.h>
#include <cuda_fp16.h>
#include <cuda_bf16.h>
#include <cstdint>

// ---------------------------------------------------------------------------
// S4D model forward:  encoder GEMM -> 4x( S4 scan+gelu -> GEMM -> GLU+res+LN )
//                     -> decoder
// GEMMs: mma.sync m16n8k16 fp16, 2-pass (A hi/lo split-2, B single fp16),
//        fp32 accum, 2 CTAs/SM, B via cp.async.
// Scan:  time-chunked (8 chunks) 3-phase linear-recurrence decomposition,
//        packed fp32x2 FMA, MUFU activations.  (R13-proven)
// ---------------------------------------------------------------------------

#define BSZ    32
#define LSEQ   1024
#define DIN    128
#define HDIM   256
#define NL     4
#define NMODE  32
#define DOUT   10
#define MROWS  (BSZ * LSEQ)          // 32768
#define HN     (HDIM * NMODE)        // 8192
#define NCH    8                     // time chunks
#define CHL    (LSEQ / NCH)          // 128 steps per chunk

// Scratch (device globals; no allocation allowed)
__device__ __align__(128) float g_h[MROWS * HDIM];
__device__ __align__(128) float g_y[MROWS * HDIM];
__device__ __align__(128) float g_z[MROWS * 2 * HDIM];
__device__ __align__(128) float g_coef[NL * 8 * HN];
__device__ __align__(128) float g_sre[BSZ * NCH * HN];
__device__ __align__(128) float g_sim[BSZ * NCH * HN];
__device__ __align__(16) __half g_wt_enc[HDIM * DIN];          // [N=256][K=128]
__device__ __align__(16) __half g_wt[NL * 2 * HDIM * HDIM];    // [512][256] x4

typedef unsigned long long ull;

__device__ __forceinline__ ull pack2(float x) {
    ull r; asm("mov.b64 %0, {%1, %1};" : "=l"(r) : "f"(x)); return r;
}
__device__ __forceinline__ ull packf(float a, float b) {
    ull r; asm("mov.b64 %0, {%1, %2};" : "=l"(r) : "f"(a), "f"(b)); return r;
}
__device__ __forceinline__ ull fma2(ull a, ull b, ull c) {
    ull d; asm("fma.rn.f32x2 %0, %1, %2, %3;" : "=l"(d) : "l"(a), "l"(b), "l"(c)); return d;
}
union U2 { ull u; float2 f; };

__device__ __forceinline__ uint32_t smem_u32(const void* p) {
    uint32_t a;
    asm("{ .reg .u64 t; cvta.to.shared.u64 t, %1; cvt.u32.u64 %0, t; }"
        : "=r"(a) : "l"(p));
    return a;
}
__device__ __forceinline__ void ldsm4(uint32_t* r, uint32_t addr) {
    asm volatile("ldmatrix.sync.aligned.m8n8.x4.shared.b16 {%0,%1,%2,%3}, [%4];"
                 : "=r"(r[0]), "=r"(r[1]), "=r"(r[2]), "=r"(r[3]) : "r"(addr));
}
__device__ __forceinline__ void mma16816h(float* c, const uint32_t* a, const uint32_t* b) {
    asm volatile("mma.sync.aligned.m16n8k16.row.col.f32.f16.f16.f32 "
                 "{%0,%1,%2,%3}, {%4,%5,%6,%7}, {%8,%9}, {%0,%1,%2,%3};"
                 : "+f"(c[0]), "+f"(c[1]), "+f"(c[2]), "+f"(c[3])
                 : "r"(a[0]), "r"(a[1]), "r"(a[2]), "r"(a[3]), "r"(b[0]), "r"(b[1]));
}
__device__ __forceinline__ void cpasync16(uint32_t d, const void* s) {
    asm volatile("cp.async.cg.shared.global [%0], [%1], 16;" :: "r"(d), "l"(s));
}
__device__ __forceinline__ uint32_t pkhf(float a, float b) {
    uint32_t ha = __half_as_ushort(__float2half_rn(a));
    uint32_t hb = __half_as_ushort(__float2half_rn(b));
    return ha | (hb << 16);
}

// gelu(x) = x * sigmoid(1.5957691*(x + 0.044715 x^3)), MUFU exp + fast div
__device__ __forceinline__ float gelu_f(float x) {
    float t = fmaf(0.044715f * x * x, x, x);
    return __fdividef(x, 1.0f + __expf(-1.5957691216057308f * t));
}

// ---------------------------------------------------------------------------
// Discretization prep.  Planes: 0 dAre, 1 dAim, 2 dBre, 3 dBim, 4 2Cre,
// 5 -2Cim, 6/7 = (dA^CHL) re/im.
// ---------------------------------------------------------------------------
__global__ void prep_coef(const float* __restrict__ log_dt,
                          const float* __restrict__ A_re_log,
                          const float* __restrict__ A_im,
                          const float* __restrict__ B_re,
                          const float* __restrict__ B_im,
                          const float* __restrict__ C_re,
                          const float* __restrict__ C_im)
{
    int t = blockIdx.x * 256 + threadIdx.x;
    if (t >= NL * HN) return;
    int l  = t / HN;
    int hn = t - l * HN;
    int hh = hn / NMODE;

    float Are = -expf(A_re_log[t]);
    float Aim = A_im[t];
    float dt  = expf(log_dt[l * HDIM + hh]);
    float dre = dt * Are, dim = dt * Aim;
    float e   = expf(dre);
    float dAre = e * cosf(dim);
    float dAim = e * sinf(dim);
    float nre = dAre - 1.0f, nim = dAim;
    float inv = 1.0f / (Are * Are + Aim * Aim);
    float qre = (nre * Are + nim * Aim) * inv;
    float qim = (nim * Are - nre * Aim) * inv;
    float bre = B_re[t], bim = B_im[t];
    float dBre = bre * qre - bim * qim;
    float dBim = bre * qim + bim * qre;

    float eL = expf((float)CHL * dre);
    float cL = cosf((float)CHL * dim);
    float sL = sinf((float)CHL * dim);

    float* cf = g_coef + (size_t)l * 8 * HN;
    cf[0 * HN + hn] = dAre;
    cf[1 * HN + hn] = dAim;
    cf[2 * HN + hn] = dBre;
    cf[3 * HN + hn] = dBim;
    cf[4 * HN + hn] =  2.0f * C_re[t];
    cf[5 * HN + hn] = -2.0f * C_im[t];
    cf[6 * HN + hn] = eL * cL;
    cf[7 * HN + hn] = eL * sL;
}

// ---------------------------------------------------------------------------
// Weight transpose -> single fp16 plane:  W [K][N] fp32 -> WT [N][K] fp16
// ---------------------------------------------------------------------------
__global__ void trans_w_f16(const float* __restrict__ W,
                            __half* __restrict__ WT, int K, int N)
{
    __shared__ float t[32][33];
    int n0 = blockIdx.x * 32, k0 = blockIdx.y * 32;
    const float* Wp = W + (size_t)blockIdx.z * K * N;
    __half* Tp = WT + (size_t)blockIdx.z * K * N;
#pragma unroll
    for (int yy = 0; yy < 32; yy += 8)
        t[threadIdx.y + yy][threadIdx.x] =
            Wp[(size_t)(k0 + threadIdx.y + yy) * N + n0 + threadIdx.x];
    __syncthreads();
#pragma unroll
    for (int yy = 0; yy < 32; yy += 8) {
        float v = t[threadIdx.x][threadIdx.y + yy];
        Tp[(size_t)(n0 + threadIdx.y + yy) * K + k0 + threadIdx.x] =
            __float2half_rn(v);
    }
}

// ---------------------------------------------------------------------------
// fp16 2-pass tensor-core GEMM (2 CTAs/SM):
//   C = (Ahi + Alo)[M,K] @ W[K,N] + bias,  W single fp16 (pre-converted),
//   A fp32 -> register-staged fp16 hi/lo split; B via cp.async.
// Stage (24KB): [Ahi 8K][Alo 8K][B 8K], double buffered (48KB).
// Rows of 64B; 16B chunk c of row r stored at c ^ ((r>>1)&3).
// ---------------------------------------------------------------------------
template <int K>
__global__ __launch_bounds__(256, 2) void mma_gemm(
    const float* __restrict__ A,
    const __half* __restrict__ Bw,
    const float* __restrict__ bias,
    float* __restrict__ C, int N)
{
    constexpr int KCH  = K / 32;
    constexpr int STG  = 24576;
    extern __shared__ char sm[];
    const uint32_t sbase = smem_u32(sm);

    const int tid  = threadIdx.x;
    const int warp = tid >> 5, lane = tid & 31;
    const int wm = warp >> 1, wn = warp & 1;
    const size_t m0 = (size_t)blockIdx.y * 128;
    const int    n0 = blockIdx.x * 128;

    // per-thread copy units: u = tid + i*256, row = u>>2 (0..127), c = u&3
    float4 afr[2][2];
    int usw[2];
#pragma unroll
    for (int i = 0; i < 2; i++) {
        int u = tid + i * 256;
        int row = u >> 2, c = u & 3;
        usw[i]  = row * 64 + ((c ^ ((row >> 1) & 3)) << 4);
    }

    auto ldgA = [&](int cs) {
#pragma unroll
        for (int i = 0; i < 2; i++) {
            int u = tid + i * 256;
            int row = u >> 2, c = u & 3;
            const float4* pa = (const float4*)(A + (m0 + row) * K + cs * 32 + c * 8);
            afr[i][0] = pa[0];
            afr[i][1] = pa[1];
        }
    };
    auto stsA = [&](int buf) {
        char* st = sm + buf * STG;
#pragma unroll
        for (int i = 0; i < 2; i++) {
            float f[8] = {afr[i][0].x, afr[i][0].y, afr[i][0].z, afr[i][0].w,
                          afr[i][1].x, afr[i][1].y, afr[i][1].z, afr[i][1].w};
            uint32_t hw[4], lw[4];
#pragma unroll
            for (int j = 0; j < 4; j++) {
                float a = f[2 * j], b = f[2 * j + 1];
                __half ha = __float2half_rn(a);
                __half hb = __float2half_rn(b);
                hw[j] = (uint32_t)__half_as_ushort(ha) |
                        ((uint32_t)__half_as_ushort(hb) << 16);
                lw[j] = pkhf(a - __half2float(ha), b - __half2float(hb));
            }
            *(uint4*)(st + usw[i])        = make_uint4(hw[0], hw[1], hw[2], hw[3]);
            *(uint4*)(st + 8192 + usw[i]) = make_uint4(lw[0], lw[1], lw[2], lw[3]);
        }
    };
    auto cpB = [&](int cs, int buf) {
        uint32_t st = sbase + buf * STG + 16384;
#pragma unroll
        for (int i = 0; i < 2; i++) {
            int u = tid + i * 256;
            int row = u >> 2, c = u & 3;
            cpasync16(st + usw[i],
                      Bw + (size_t)(n0 + row) * K + cs * 32 + c * 8);
        }
        asm volatile("cp.async.commit_group;");
    };

    float acc[2][8][4];
#pragma unroll
    for (int a = 0; a < 2; a++)
#pragma unroll
        for (int b = 0; b < 8; b++)
#pragma unroll
            for (int c = 0; c < 4; c++) acc[a][b][c] = 0.f;

    auto compute = [&](int buf) {
        uint32_t ab = sbase + buf * STG;
#pragma unroll
        for (int ks = 0; ks < 2; ks++) {
            uint32_t ah[2][4], al[2][4], bb[8][2];
#pragma unroll
            for (int mt = 0; mt < 2; mt++) {
                int r  = wm * 32 + mt * 16 + (lane & 15);
                int ch = ks * 2 + (lane >> 4);
                uint32_t addr = ab + r * 64 + ((ch ^ ((r >> 1) & 3)) << 4);
                ldsm4(ah[mt], addr);
                ldsm4(al[mt], addr + 8192);
            }
#pragma unroll
            for (int j = 0; j < 4; j++) {
                int r  = wn * 64 + j * 16 + (lane & 15);
                int ch = ks * 2 + (lane >> 4);
                uint32_t addr = ab + 16384 + r * 64 + ((ch ^ ((r >> 1) & 3)) << 4);
                uint32_t q[4];
                ldsm4(q, addr);
                bb[2 * j][0] = q[0]; bb[2 * j + 1][0] = q[1];
                bb[2 * j][1] = q[2]; bb[2 * j + 1][1] = q[3];
            }
#pragma unroll
            for (int mt = 0; mt < 2; mt++)
#pragma unroll
                for (int nt = 0; nt < 8; nt++) {
                    mma16816h(acc[mt][nt], ah[mt], bb[nt]);
                    mma16816h(acc[mt][nt], al[mt], bb[nt]);
                }
        }
    };

    // prologue: fill buffer 0
    ldgA(0);
    cpB(0, 0);
    stsA(0);
    if (KCH > 1) ldgA(1);
    asm volatile("cp.async.wait_group 0;" ::: "memory");
    __syncthreads();

    for (int c = 0; c < KCH; c++) {
        if (c + 1 < KCH) cpB(c + 1, (c + 1) & 1);
        compute(c & 1);
        if (c + 1 < KCH) {
            stsA((c + 1) & 1);
            if (c + 2 < KCH) ldgA(c + 2);
            asm volatile("cp.async.wait_group 0;" ::: "memory");
        }
        __syncthreads();
    }

#pragma unroll
    for (int mt = 0; mt < 2; mt++) {
#pragma unroll
        for (int nt = 0; nt < 8; nt++) {
            int r = (int)m0 + wm * 32 + mt * 16 + (lane >> 2);
            int n = n0 + wn * 64 + nt * 8 + (lane & 3) * 2;
            float b0 = bias[n], b1 = bias[n + 1];
            *(float2*)(C + (size_t)r * N + n) =
                make_float2(acc[mt][nt][0] + b0, acc[mt][nt][1] + b1);
            *(float2*)(C + (size_t)(r + 8) * N + n) =
                make_float2(acc[mt][nt][2] + b0, acc[mt][nt][3] + b1);
        }
    }
}

// ---------------------------------------------------------------------------
// Scan lane mapping: block = 128 thr owns (batch, 32 chans, one time chunk).
// 4 lanes per channel, 8 modes per lane (4 packed pairs).
// ---------------------------------------------------------------------------
#define SCAN_COEF_LOAD(NP)                                                    \
    ull dAre2[NP], dAim2[NP], ndAim2[NP], dBre2[NP], dBim2[NP];               \
    _Pragma("unroll")                                                         \
    for (int p = 0; p < NP; p++) {                                            \
        int c0 = hh * NMODE + mg + 2 * p;                                     \
        dAre2[p]  = packf(cf[0 * HN + c0], cf[0 * HN + c0 + 1]);              \
        dAim2[p]  = packf(cf[1 * HN + c0], cf[1 * HN + c0 + 1]);              \
        ndAim2[p] = packf(-cf[1 * HN + c0], -cf[1 * HN + c0 + 1]);            \
        dBre2[p]  = packf(cf[2 * HN + c0], cf[2 * HN + c0 + 1]);              \
        dBim2[p]  = packf(cf[3 * HN + c0], cf[3 * HN + c0 + 1]);              \
    }

// Phase A: local end-state per chunk (zero init), chunks 0..NCH-2
__global__ __launch_bounds__(128) void s4_state(
    const float* __restrict__ u, const float* __restrict__ cf)
{
    const int b     = blockIdx.y;
    const int chunk = blockIdx.z;
    const int h0    = blockIdx.x * 32;
    const int tid   = threadIdx.x;
    const int w     = tid >> 5;
    const int lane  = tid & 31;
    const int hcol  = (w << 3) + (lane >> 2);
    const int mg    = (lane & 3) * 8;
    const int hh    = h0 + hcol;

    SCAN_COEF_LOAD(4)

    __shared__ float su[64 * 32];
    ull sre2[4] = {0ull, 0ull, 0ull, 0ull};
    ull sim2[4] = {0ull, 0ull, 0ull, 0ull};

    const float* ub = u + ((size_t)b * LSEQ + (size_t)chunk * CHL) * HDIM + h0;

    for (int l0 = 0; l0 < CHL; l0 += 64) {
        __syncthreads();
#pragma unroll
        for (int k = 0; k < 16; k++) {
            int e = tid + k * 128;
            su[e] = ub[(size_t)(l0 + (e >> 5)) * HDIM + (e & 31)];
        }
        __syncthreads();
#pragma unroll 4
        for (int i = 0; i < 64; i++) {
            ull uu2 = pack2(su[i * 32 + hcol]);
#pragma unroll
            for (int p = 0; p < 4; p++) {
                ull mre = fma2(dBre2[p], uu2, 0ull);
                ull mim = fma2(dBim2[p], uu2, 0ull);
                ull nre = fma2(ndAim2[p], sim2[p], mre);
                nre     = fma2(dAre2[p],  sre2[p], nre);
                ull nim = fma2(dAim2[p],  sre2[p], mim);
                nim     = fma2(dAre2[p],  sim2[p], nim);
                sre2[p] = nre; sim2[p] = nim;
            }
        }
    }
    size_t sidx = ((size_t)b * NCH + chunk) * HN + hh * NMODE + mg;
#pragma unroll
    for (int p = 0; p < 4; p++) {
        U2 r, q; r.u = sre2[p]; q.u = sim2[p];
        g_sre[sidx + 2 * p]     = r.f.x;
        g_sre[sidx + 2 * p + 1] = r.f.y;
        g_sim[sidx + 2 * p]     = q.f.x;
        g_sim[sidx + 2 * p + 1] = q.f.y;
    }
}

// Phase B: cross-chunk scan (in place): end-states -> init states
__global__ __launch_bounds__(256) void s4_fix(const float* __restrict__ cf)
{
    int t = blockIdx.x * 256 + threadIdx.x;
    if (t >= BSZ * HN) return;
    int b  = t / HN;
    int hn = t - b * HN;
    float pre = cf[6 * HN + hn], pim = cf[7 * HN + hn];
    float Sre = 0.f, Sim = 0.f;
#pragma unroll
    for (int c = 0; c < NCH; c++) {
        size_t idx = ((size_t)b * NCH + c) * HN + hn;
        float ere = 0.f, eim = 0.f;
        if (c < NCH - 1) { ere = g_sre[idx]; eim = g_sim[idx]; }
        g_sre[idx] = Sre;
        g_sim[idx] = Sim;
        float nr = fmaf(pre, Sre, fmaf(-pim, Sim, ere));
        float ni = fmaf(pre, Sim, fmaf(pim, Sre, eim));
        Sre = nr; Sim = ni;
    }
}

// Phase C: full per-chunk scan with init state -> gelu(y + D*u) in fp32
__global__ __launch_bounds__(128) void s4_scan_out(
    const float* __restrict__ u, float* __restrict__ y,
    const float* __restrict__ cf, const float* __restrict__ Dv)
{
    const int b     = blockIdx.y;
    const int chunk = blockIdx.z;
    const int h0    = blockIdx.x * 32;
    const int tid   = threadIdx.x;
    const int w     = tid >> 5;
    const int lane  = tid & 31;
    const int hcol  = (w << 3) + (lane >> 2);
    const int mg    = (lane & 3) * 8;
    const int hh    = h0 + hcol;

    SCAN_COEF_LOAD(4)
    ull c2re2[4], c2in2[4];
#pragma unroll
    for (int p = 0; p < 4; p++) {
        int c0 = hh * NMODE + mg + 2 * p;
        c2re2[p] = packf(cf[4 * HN + c0], cf[4 * HN + c0 + 1]);
        c2in2[p] = packf(cf[5 * HN + c0], cf[5 * HN + c0 + 1]);
    }

    __shared__ float su[64 * 32];
    __shared__ float sy[64 * 32];
    __shared__ float sD[32];
    if (tid < 32) sD[tid] = Dv[h0 + tid];

    ull sre2[4], sim2[4];
    {
        size_t sidx = ((size_t)b * NCH + chunk) * HN + hh * NMODE + mg;
#pragma unroll
        for (int p = 0; p < 4; p++) {
            sre2[p] = packf(g_sre[sidx + 2 * p], g_sre[sidx + 2 * p + 1]);
            sim2[p] = packf(g_sim[sidx + 2 * p], g_sim[sidx + 2 * p + 1]);
        }
    }

    const size_t rbase = ((size_t)b * LSEQ + (size_t)chunk * CHL) * HDIM + h0;
    const float* ub = u + rbase;
    float*       yb = y + rbase;

    for (int l0 = 0; l0 < CHL; l0 += 64) {
        __syncthreads();
#pragma unroll
        for (int k = 0; k < 16; k++) {
            int e = tid + k * 128;
            su[e] = ub[(size_t)(l0 + (e >> 5)) * HDIM + (e & 31)];
        }
        __syncthreads();
#pragma unroll 2
        for (int i = 0; i < 64; i++) {
            ull uu2  = pack2(su[i * 32 + hcol]);
            ull cacc = 0ull;
#pragma unroll
            for (int p = 0; p < 4; p++) {
                ull mre = fma2(dBre2[p], uu2, 0ull);
                ull mim = fma2(dBim2[p], uu2, 0ull);
                ull nre = fma2(ndAim2[p], sim2[p], mre);
                nre     = fma2(dAre2[p],  sre2[p], nre);
                ull nim = fma2(dAim2[p],  sre2[p], mim);
                nim     = fma2(dAre2[p],  sim2[p], nim);
                sre2[p] = nre; sim2[p] = nim;
                cacc = fma2(c2re2[p], nre, cacc);
                cacc = fma2(c2in2[p], nim, cacc);
            }
            U2 cu; cu.u = cacc;
            float c = cu.f.x + cu.f.y;
            c += __shfl_xor_sync(0xffffffffu, c, 1);
            c += __shfl_xor_sync(0xffffffffu, c, 2);
            if ((lane & 3) == 0) sy[i * 32 + hcol] = c;
        }
        __syncthreads();
#pragma unroll
        for (int k = 0; k < 16; k++) {
            int e = tid + k * 128;
            float t = sy[e] + sD[e & 31] * su[e];
            yb[(size_t)(l0 + (e >> 5)) * HDIM + (e & 31)] = gelu_f(t);
        }
    }
}

// ---------------------------------------------------------------------------
// GLU + residual + LayerNorm (in-place on h).  Warp per row of 256.
// ---------------------------------------------------------------------------
__global__ __launch_bounds__(256) void glu_res_ln(
    const float* __restrict__ z, float* __restrict__ h,
    const float* __restrict__ lnw, const float* __restrict__ lnb)
{
    const int row  = blockIdx.x * 8 + (threadIdx.x >> 5);
    const int lane = threadIdx.x & 31;
    const float* zr = z + (size_t)row * (2 * HDIM);
    float*       hr = h + (size_t)row * HDIM;

    float tv[8];
    float s = 0.f, s2 = 0.f;
#pragma unroll
    for (int k = 0; k < 8; k++) {
        int c = lane + k * 32;
        float a  = zr[c];
        float gg = zr[HDIM + c];
        float t  = __fdividef(a, 1.0f + __expf(-gg)) + hr[c];
        tv[k] = t;
        s  += t;
        s2  = fmaf(t, t, s2);
    }
#pragma unroll
    for (int o = 16; o; o >>= 1) {
        s  += __shfl_xor_sync(0xffffffffu, s,  o);
        s2 += __shfl_xor_sync(0xffffffffu, s2, o);
    }
    float mean = s * (1.0f / 256.0f);
    float var  = fmaf(-mean, mean, s2 * (1.0f / 256.0f));
    float rs   = rsqrtf(var + 1e-5f);
#pragma unroll
    for (int k = 0; k < 8; k++) {
        int c = lane + k * 32;
        hr[c] = fmaf((tv[k] - mean) * rs, lnw[c], lnb[c]);
    }
}

// ---------------------------------------------------------------------------
// Decoder: out[M,10] = h[M,256] @ dec_w[256,10] + dec_b
// ---------------------------------------------------------------------------
__global__ __launch_bounds__(256) void decoder(
    const float* __restrict__ h, const float* __restrict__ wv,
    const float* __restrict__ bvec, float* __restrict__ out)
{
    __shared__ float sw[HDIM * DOUT];
    for (int i = threadIdx.x; i < HDIM * DOUT; i += 256) sw[i] = wv[i];
    __syncthreads();
    int o = blockIdx.x * 256 + threadIdx.x;
    int r = o / DOUT, n = o - r * DOUT;
    const float* hr = h + (size_t)r * HDIM;
    float s = bvec[n];
#pragma unroll 8
    for (int k = 0; k < HDIM; k++) s = fmaf(hr[k], sw[k * DOUT + n], s);
    out[o] = s;
}

// ---------------------------------------------------------------------------
extern "C" void kernel_launch(void* const* d_in, const int* in_sizes, int n_in,
                              void* d_out, int out_size)
{
    const float* x        = (const float*)d_in[0];
    const float* enc_w    = (const float*)d_in[1];
    const float* enc_b    = (const float*)d_in[2];
    const float* log_dt   = (const float*)d_in[3];
    const float* A_re_log = (const float*)d_in[4];
    const float* A_im     = (const float*)d_in[5];
    const float* B_re     = (const float*)d_in[6];
    const float* B_im     = (const float*)d_in[7];
    const float* C_re     = (const float*)d_in[8];
    const float* C_im     = (const float*)d_in[9];
    const float* Dp       = (const float*)d_in[10];
    const float* ln_w     = (const float*)d_in[11];
    const float* ln_b     = (const float*)d_in[12];
    const float* out_w    = (const float*)d_in[13];
    const float* out_b    = (const float*)d_in[14];
    const float* dec_w    = (const float*)d_in[15];
    const float* dec_b    = (const float*)d_in[16];
    float* outp = (float*)d_out;

    float *ph, *py, *pz, *pcf;
    __half *pwE, *pwl;
    cudaGetSymbolAddress((void**)&ph,  g_h);
    cudaGetSymbolAddress((void**)&py,  g_y);
    cudaGetSymbolAddress((void**)&pz,  g_z);
    cudaGetSymbolAddress((void**)&pcf, g_coef);
    cudaGetSymbolAddress((void**)&pwE, g_wt_enc);
    cudaGetSymbolAddress((void**)&pwl, g_wt);

    cudaFuncSetAttribute(mma_gemm<128>,
                         cudaFuncAttributeMaxDynamicSharedMemorySize, 49152);
    cudaFuncSetAttribute(mma_gemm<256>,
                         cudaFuncAttributeMaxDynamicSharedMemorySize, 49152);

    prep_coef<<<(NL * HN + 255) / 256, 256>>>(log_dt, A_re_log, A_im,
                                              B_re, B_im, C_re, C_im);
    trans_w_f16<<<dim3(HDIM / 32, DIN / 32, 1), dim3(32, 8)>>>(enc_w, pwE,
                                                               DIN, HDIM);
    trans_w_f16<<<dim3(2 * HDIM / 32, HDIM / 32, NL), dim3(32, 8)>>>(out_w, pwl,
                                                                     HDIM, 2 * HDIM);

    // encoder: h = x @ enc_w + enc_b   (M=32768, N=256, K=128)
    mma_gemm<128><<<dim3(2, MROWS / 128), 256, 49152>>>(x, pwE, enc_b,
                                                        ph, HDIM);

    for (int l = 0; l < NL; l++) {
        const float* cfl = pcf + (size_t)l * 8 * HN;
        s4_state<<<dim3(HDIM / 32, BSZ, NCH - 1), 128>>>(ph, cfl);
        s4_fix<<<(BSZ * HN + 255) / 256, 256>>>(cfl);
        s4_scan_out<<<dim3(HDIM / 32, BSZ, NCH), 128>>>(ph, py, cfl,
                                                        Dp + l * HDIM);
        mma_gemm<256><<<dim3(4, MROWS / 128), 256, 49152>>>(
            py, pwl + (size_t)l * 2 * HDIM * HDIM,
            out_b + l * 2 * HDIM, pz, 2 * HDIM);
        glu_res_ln<<<MROWS / 8, 256>>>(pz, ph, ln_w + l * HDIM, ln_b + l * HDIM);
    }

    decoder<<<(MROWS * DOUT) / 256, 256>>>(ph, dec_w, dec_b, outp);
}

// round 16
// speedup vs baseline: 1.2310x; 1.0045x over previous
#include <cuda_runtime.h>
#include <cuda_fp16.h>
#include <cstdint>

// ---------------------------------------------------------------------------
// S4D model forward:  encoder GEMM -> 4x( S4 scan+gelu -> GEMM(+GLU fused)
//                     -> LN ) -> decoder
// GEMMs: mma.sync m16n8k16 fp16, 2-pass (A hi/lo split-2, B single fp16),
//        fp32 accum, 2 CTAs/SM, B via cp.async.  Layer GEMM fuses
//        bias+GLU+residual in-epilogue (a/g column pairing per CTA).
// Scan:  time-chunked (8 chunks) 3-phase linear-recurrence decomposition,
//        packed fp32x2 FMA, MUFU activations.
// ---------------------------------------------------------------------------

#define BSZ    32
#define LSEQ   1024
#define DIN    128
#define HDIM   256
#define NL     4
#define NMODE  32
#define DOUT   10
#define MROWS  (BSZ * LSEQ)          // 32768
#define HN     (HDIM * NMODE)        // 8192
#define NCH    8                     // time chunks
#define CHL    (LSEQ / NCH)          // 128 steps per chunk

// Scratch (device globals; no allocation allowed)
__device__ __align__(128) float g_h[MROWS * HDIM];
__device__ __align__(128) float g_y[MROWS * HDIM];
__device__ __align__(128) float g_t[MROWS * HDIM];   // GLU output (pre-LN)
__device__ __align__(128) float g_coef[NL * 8 * HN];
__device__ __align__(128) float g_sre[BSZ * NCH * HN];
__device__ __align__(128) float g_sim[BSZ * NCH * HN];
__device__ __align__(16) __half g_wt_enc[HDIM * DIN];          // [N=256][K=128]
__device__ __align__(16) __half g_wt[NL * 2 * HDIM * HDIM];    // [512][256] x4

typedef unsigned long long ull;

__device__ __forceinline__ ull pack2(float x) {
    ull r; asm("mov.b64 %0, {%1, %1};" : "=l"(r) : "f"(x)); return r;
}
__device__ __forceinline__ ull packf(float a, float b) {
    ull r; asm("mov.b64 %0, {%1, %2};" : "=l"(r) : "f"(a), "f"(b)); return r;
}
__device__ __forceinline__ ull fma2(ull a, ull b, ull c) {
    ull d; asm("fma.rn.f32x2 %0, %1, %2, %3;" : "=l"(d) : "l"(a), "l"(b), "l"(c)); return d;
}
union U2 { ull u; float2 f; };

__device__ __forceinline__ uint32_t smem_u32(const void* p) {
    uint32_t a;
    asm("{ .reg .u64 t; cvta.to.shared.u64 t, %1; cvt.u32.u64 %0, t; }"
        : "=r"(a) : "l"(p));
    return a;
}
__device__ __forceinline__ void ldsm4(uint32_t* r, uint32_t addr) {
    asm volatile("ldmatrix.sync.aligned.m8n8.x4.shared.b16 {%0,%1,%2,%3}, [%4];"
                 : "=r"(r[0]), "=r"(r[1]), "=r"(r[2]), "=r"(r[3]) : "r"(addr));
}
__device__ __forceinline__ void mma16816h(float* c, const uint32_t* a, const uint32_t* b) {
    asm volatile("mma.sync.aligned.m16n8k16.row.col.f32.f16.f16.f32 "
                 "{%0,%1,%2,%3}, {%4,%5,%6,%7}, {%8,%9}, {%0,%1,%2,%3};"
                 : "+f"(c[0]), "+f"(c[1]), "+f"(c[2]), "+f"(c[3])
                 : "r"(a[0]), "r"(a[1]), "r"(a[2]), "r"(a[3]), "r"(b[0]), "r"(b[1]));
}
__device__ __forceinline__ void cpasync16(uint32_t d, const void* s) {
    asm volatile("cp.async.cg.shared.global [%0], [%1], 16;" :: "r"(d), "l"(s));
}
__device__ __forceinline__ uint32_t pkhf(float a, float b) {
    uint32_t ha = __half_as_ushort(__float2half_rn(a));
    uint32_t hb = __half_as_ushort(__float2half_rn(b));
    return ha | (hb << 16);
}
__device__ __forceinline__ float sigm_f(float x) {
    return __fdividef(1.0f, 1.0f + __expf(-x));
}
// gelu(x) = x * sigmoid(1.5957691*(x + 0.044715 x^3)), MUFU exp + fast div
__device__ __forceinline__ float gelu_f(float x) {
    float t = fmaf(0.044715f * x * x, x, x);
    return __fdividef(x, 1.0f + __expf(-1.5957691216057308f * t));
}

// ---------------------------------------------------------------------------
// Discretization prep.  Planes: 0 dAre, 1 dAim, 2 dBre, 3 dBim, 4 2Cre,
// 5 -2Cim, 6/7 = (dA^CHL) re/im.
// ---------------------------------------------------------------------------
__global__ void prep_coef(const float* __restrict__ log_dt,
                          const float* __restrict__ A_re_log,
                          const float* __restrict__ A_im,
                          const float* __restrict__ B_re,
                          const float* __restrict__ B_im,
                          const float* __restrict__ C_re,
                          const float* __restrict__ C_im)
{
    int t = blockIdx.x * 256 + threadIdx.x;
    if (t >= NL * HN) return;
    int l  = t / HN;
    int hn = t - l * HN;
    int hh = hn / NMODE;

    float Are = -expf(A_re_log[t]);
    float Aim = A_im[t];
    float dt  = expf(log_dt[l * HDIM + hh]);
    float dre = dt * Are, dim = dt * Aim;
    float e   = expf(dre);
    float dAre = e * cosf(dim);
    float dAim = e * sinf(dim);
    float nre = dAre - 1.0f, nim = dAim;
    float inv = 1.0f / (Are * Are + Aim * Aim);
    float qre = (nre * Are + nim * Aim) * inv;
    float qim = (nim * Are - nre * Aim) * inv;
    float bre = B_re[t], bim = B_im[t];
    float dBre = bre * qre - bim * qim;
    float dBim = bre * qim + bim * qre;

    float eL = expf((float)CHL * dre);
    float cL = cosf((float)CHL * dim);
    float sL = sinf((float)CHL * dim);

    float* cf = g_coef + (size_t)l * 8 * HN;
    cf[0 * HN + hn] = dAre;
    cf[1 * HN + hn] = dAim;
    cf[2 * HN + hn] = dBre;
    cf[3 * HN + hn] = dBim;
    cf[4 * HN + hn] =  2.0f * C_re[t];
    cf[5 * HN + hn] = -2.0f * C_im[t];
    cf[6 * HN + hn] = eL * cL;
    cf[7 * HN + hn] = eL * sL;
}

// ---------------------------------------------------------------------------
// Weight transpose -> single fp16 plane:  W [K][N] fp32 -> WT [N][K] fp16
// ---------------------------------------------------------------------------
__global__ void trans_w_f16(const float* __restrict__ W,
                            __half* __restrict__ WT, int K, int N)
{
    __shared__ float t[32][33];
    int n0 = blockIdx.x * 32, k0 = blockIdx.y * 32;
    const float* Wp = W + (size_t)blockIdx.z * K * N;
    __half* Tp = WT + (size_t)blockIdx.z * K * N;
#pragma unroll
    for (int yy = 0; yy < 32; yy += 8)
        t[threadIdx.y + yy][threadIdx.x] =
            Wp[(size_t)(k0 + threadIdx.y + yy) * N + n0 + threadIdx.x];
    __syncthreads();
#pragma unroll
    for (int yy = 0; yy < 32; yy += 8) {
        float v = t[threadIdx.x][threadIdx.y + yy];
        Tp[(size_t)(n0 + threadIdx.y + yy) * K + k0 + threadIdx.x] =
            __float2half_rn(v);
    }
}

// ---------------------------------------------------------------------------
// fp16 2-pass tensor-core GEMM (2 CTAs/SM).
// GLU=false: C[M,N] = A@W + bias (encoder).
// GLU=true : N=512 logical; CTA x owns a-cols [x*64,x*64+64) and g-cols
//            [256+x*64, ...+64).  Epilogue: t = (a+ba)*sigmoid(g+bg) + hres,
//            written to T[M,256].  B rows remapped accordingly.
// Stage (24KB): [Ahi 8K][Alo 8K][B 8K], double buffered (48KB).
// ---------------------------------------------------------------------------
template <int K, bool GLU>
__global__ __launch_bounds__(256, 2) void mma_gemm(
    const float* __restrict__ A,
    const __half* __restrict__ Bw,
    const float* __restrict__ bias,
    float* __restrict__ C, int N,
    const float* __restrict__ hres)
{
    constexpr int KCH  = K / 32;
    constexpr int STG  = 24576;
    extern __shared__ char sm[];
    const uint32_t sbase = smem_u32(sm);

    const int tid  = threadIdx.x;
    const int warp = tid >> 5, lane = tid & 31;
    const int wm = warp >> 1, wn = warp & 1;
    const size_t m0 = (size_t)blockIdx.y * 128;
    const int    n0 = blockIdx.x * 128;   // non-GLU col base
    const int    x64 = blockIdx.x * 64;   // GLU a-col base

    float4 afr[2][2];
    int usw[2];
#pragma unroll
    for (int i = 0; i < 2; i++) {
        int u = tid + i * 256;
        int row = u >> 2, c = u & 3;
        usw[i]  = row * 64 + ((c ^ ((row >> 1) & 3)) << 4);
    }

    auto ldgA = [&](int cs) {
#pragma unroll
        for (int i = 0; i < 2; i++) {
            int u = tid + i * 256;
            int row = u >> 2, c = u & 3;
            const float4* pa = (const float4*)(A + (m0 + row) * K + cs * 32 + c * 8);
            afr[i][0] = pa[0];
            afr[i][1] = pa[1];
        }
    };
    auto stsA = [&](int buf) {
        char* st = sm + buf * STG;
#pragma unroll
        for (int i = 0; i < 2; i++) {
            float f[8] = {afr[i][0].x, afr[i][0].y, afr[i][0].z, afr[i][0].w,
                          afr[i][1].x, afr[i][1].y, afr[i][1].z, afr[i][1].w};
            uint32_t hw[4], lw[4];
#pragma unroll
            for (int j = 0; j < 4; j++) {
                float a = f[2 * j], b = f[2 * j + 1];
                __half ha = __float2half_rn(a);
                __half hb = __float2half_rn(b);
                hw[j] = (uint32_t)__half_as_ushort(ha) |
                        ((uint32_t)__half_as_ushort(hb) << 16);
                lw[j] = pkhf(a - __half2float(ha), b - __half2float(hb));
            }
            *(uint4*)(st + usw[i])        = make_uint4(hw[0], hw[1], hw[2], hw[3]);
            *(uint4*)(st + 8192 + usw[i]) = make_uint4(lw[0], lw[1], lw[2], lw[3]);
        }
    };
    auto cpB = [&](int cs, int buf) {
        uint32_t st = sbase + buf * STG + 16384;
#pragma unroll
        for (int i = 0; i < 2; i++) {
            int u = tid + i * 256;
            int row = u >> 2, c = u & 3;
            int prow = GLU ? ((row < 64) ? (x64 + row) : (192 + x64 + row))
                           : (n0 + row);
            cpasync16(st + usw[i],
                      Bw + (size_t)prow * K + cs * 32 + c * 8);
        }
        asm volatile("cp.async.commit_group;");
    };

    float acc[2][8][4];
#pragma unroll
    for (int a = 0; a < 2; a++)
#pragma unroll
        for (int b = 0; b < 8; b++)
#pragma unroll
            for (int c = 0; c < 4; c++) acc[a][b][c] = 0.f;

    auto compute = [&](int buf) {
        uint32_t ab = sbase + buf * STG;
#pragma unroll
        for (int ks = 0; ks < 2; ks++) {
            uint32_t ah[2][4], al[2][4], bb[8][2];
#pragma unroll
            for (int mt = 0; mt < 2; mt++) {
                int r  = wm * 32 + mt * 16 + (lane & 15);
                int ch = ks * 2 + (lane >> 4);
                uint32_t addr = ab + r * 64 + ((ch ^ ((r >> 1) & 3)) << 4);
                ldsm4(ah[mt], addr);
                ldsm4(al[mt], addr + 8192);
            }
#pragma unroll
            for (int j = 0; j < 4; j++) {
                int r  = wn * 64 + j * 16 + (lane & 15);
                int ch = ks * 2 + (lane >> 4);
                uint32_t addr = ab + 16384 + r * 64 + ((ch ^ ((r >> 1) & 3)) << 4);
                uint32_t q[4];
                ldsm4(q, addr);
                bb[2 * j][0] = q[0]; bb[2 * j + 1][0] = q[1];
                bb[2 * j][1] = q[2]; bb[2 * j + 1][1] = q[3];
            }
#pragma unroll
            for (int mt = 0; mt < 2; mt++)
#pragma unroll
                for (int nt = 0; nt < 8; nt++) {
                    mma16816h(acc[mt][nt], ah[mt], bb[nt]);
                    mma16816h(acc[mt][nt], al[mt], bb[nt]);
                }
        }
    };

    // prologue: fill buffer 0
    ldgA(0);
    cpB(0, 0);
    stsA(0);
    if (KCH > 1) ldgA(1);
    asm volatile("cp.async.wait_group 0;" ::: "memory");
    __syncthreads();

    for (int c = 0; c < KCH; c++) {
        if (c + 1 < KCH) cpB(c + 1, (c + 1) & 1);
        compute(c & 1);
        if (c + 1 < KCH) {
            stsA((c + 1) & 1);
            if (c + 2 < KCH) ldgA(c + 2);
            asm volatile("cp.async.wait_group 0;" ::: "memory");
        }
        __syncthreads();
    }

    if (GLU) {
        // smem sigmoid-exchange: wn=1 warps hold g-cols, wn=0 hold a-cols.
        float* tb = (float*)sm;                 // [128][66] fp32 = 33.8KB
        if (wn == 1) {
#pragma unroll
            for (int mt = 0; mt < 2; mt++)
#pragma unroll
                for (int nt = 0; nt < 8; nt++) {
                    int r  = wm * 32 + mt * 16 + (lane >> 2);
                    int gc = nt * 8 + (lane & 3) * 2;
                    float bg0 = bias[256 + x64 + gc];
                    float bg1 = bias[256 + x64 + gc + 1];
                    tb[r * 66 + gc]           = sigm_f(acc[mt][nt][0] + bg0);
                    tb[r * 66 + gc + 1]       = sigm_f(acc[mt][nt][1] + bg1);
                    tb[(r + 8) * 66 + gc]     = sigm_f(acc[mt][nt][2] + bg0);
                    tb[(r + 8) * 66 + gc + 1] = sigm_f(acc[mt][nt][3] + bg1);
                }
        }
        __syncthreads();
        if (wn == 0) {
#pragma unroll
            for (int mt = 0; mt < 2; mt++)
#pragma unroll
                for (int nt = 0; nt < 8; nt++) {
                    int r  = wm * 32 + mt * 16 + (lane >> 2);
                    int ac = nt * 8 + (lane & 3) * 2;
                    float ba0 = bias[x64 + ac], ba1 = bias[x64 + ac + 1];
                    size_t go0 = (m0 + r) * HDIM + x64 + ac;
                    size_t go1 = (m0 + r + 8) * HDIM + x64 + ac;
                    float2 h0 = *(const float2*)(hres + go0);
                    float2 h1 = *(const float2*)(hres + go1);
                    float2 o0 = make_float2(
                        fmaf(acc[mt][nt][0] + ba0, tb[r * 66 + ac],       h0.x),
                        fmaf(acc[mt][nt][1] + ba1, tb[r * 66 + ac + 1],   h0.y));
                    float2 o1 = make_float2(
                        fmaf(acc[mt][nt][2] + ba0, tb[(r + 8) * 66 + ac],     h1.x),
                        fmaf(acc[mt][nt][3] + ba1, tb[(r + 8) * 66 + ac + 1], h1.y));
                    *(float2*)(C + go0) = o0;
                    *(float2*)(C + go1) = o1;
                }
        }
    } else {
#pragma unroll
        for (int mt = 0; mt < 2; mt++) {
#pragma unroll
            for (int nt = 0; nt < 8; nt++) {
                int r = (int)m0 + wm * 32 + mt * 16 + (lane >> 2);
                int n = n0 + wn * 64 + nt * 8 + (lane & 3) * 2;
                float b0 = bias[n], b1 = bias[n + 1];
                *(float2*)(C + (size_t)r * N + n) =
                    make_float2(acc[mt][nt][0] + b0, acc[mt][nt][1] + b1);
                *(float2*)(C + (size_t)(r + 8) * N + n) =
                    make_float2(acc[mt][nt][2] + b0, acc[mt][nt][3] + b1);
            }
        }
    }
}

// ---------------------------------------------------------------------------
// Scan lane mapping: block = 128 thr owns (batch, 32 chans, one time chunk).
// 4 lanes per channel, 8 modes per lane (4 packed pairs).
// ---------------------------------------------------------------------------
#define SCAN_COEF_LOAD(NP)                                                    \
    ull dAre2[NP], dAim2[NP], ndAim2[NP], dBre2[NP], dBim2[NP];               \
    _Pragma("unroll")                                                         \
    for (int p = 0; p < NP; p++) {                                            \
        int c0 = hh * NMODE + mg + 2 * p;                                     \
        dAre2[p]  = packf(cf[0 * HN + c0], cf[0 * HN + c0 + 1]);              \
        dAim2[p]  = packf(cf[1 * HN + c0], cf[1 * HN + c0 + 1]);              \
        ndAim2[p] = packf(-cf[1 * HN + c0], -cf[1 * HN + c0 + 1]);            \
        dBre2[p]  = packf(cf[2 * HN + c0], cf[2 * HN + c0 + 1]);              \
        dBim2[p]  = packf(cf[3 * HN + c0], cf[3 * HN + c0 + 1]);              \
    }

// Phase A: local end-state per chunk (zero init), chunks 0..NCH-2
__global__ __launch_bounds__(128) void s4_state(
    const float* __restrict__ u, const float* __restrict__ cf)
{
    const int b     = blockIdx.y;
    const int chunk = blockIdx.z;
    const int h0    = blockIdx.x * 32;
    const int tid   = threadIdx.x;
    const int w     = tid >> 5;
    const int lane  = tid & 31;
    const int hcol  = (w << 3) + (lane >> 2);
    const int mg    = (lane & 3) * 8;
    const int hh    = h0 + hcol;

    SCAN_COEF_LOAD(4)

    __shared__ float su[64 * 32];
    ull sre2[4] = {0ull, 0ull, 0ull, 0ull};
    ull sim2[4] = {0ull, 0ull, 0ull, 0ull};

    const float* ub = u + ((size_t)b * LSEQ + (size_t)chunk * CHL) * HDIM + h0;

    for (int l0 = 0; l0 < CHL; l0 += 64) {
        __syncthreads();
#pragma unroll
        for (int k = 0; k < 16; k++) {
            int e = tid + k * 128;
            su[e] = ub[(size_t)(l0 + (e >> 5)) * HDIM + (e & 31)];
        }
        __syncthreads();
#pragma unroll 4
        for (int i = 0; i < 64; i++) {
            ull uu2 = pack2(su[i * 32 + hcol]);
#pragma unroll
            for (int p = 0; p < 4; p++) {
                ull mre = fma2(dBre2[p], uu2, 0ull);
                ull mim = fma2(dBim2[p], uu2, 0ull);
                ull nre = fma2(ndAim2[p], sim2[p], mre);
                nre     = fma2(dAre2[p],  sre2[p], nre);
                ull nim = fma2(dAim2[p],  sre2[p], mim);
                nim     = fma2(dAre2[p],  sim2[p], nim);
                sre2[p] = nre; sim2[p] = nim;
            }
        }
    }
    size_t sidx = ((size_t)b * NCH + chunk) * HN + hh * NMODE + mg;
#pragma unroll
    for (int p = 0; p < 4; p++) {
        U2 r, q; r.u = sre2[p]; q.u = sim2[p];
        g_sre[sidx + 2 * p]     = r.f.x;
        g_sre[sidx + 2 * p + 1] = r.f.y;
        g_sim[sidx + 2 * p]     = q.f.x;
        g_sim[sidx + 2 * p + 1] = q.f.y;
    }
}

// Phase B: cross-chunk scan (in place): end-states -> init states
__global__ __launch_bounds__(256) void s4_fix(const float* __restrict__ cf)
{
    int t = blockIdx.x * 256 + threadIdx.x;
    if (t >= BSZ * HN) return;
    int b  = t / HN;
    int hn = t - b * HN;
    float pre = cf[6 * HN + hn], pim = cf[7 * HN + hn];
    float Sre = 0.f, Sim = 0.f;
#pragma unroll
    for (int c = 0; c < NCH; c++) {
        size_t idx = ((size_t)b * NCH + c) * HN + hn;
        float ere = 0.f, eim = 0.f;
        if (c < NCH - 1) { ere = g_sre[idx]; eim = g_sim[idx]; }
        g_sre[idx] = Sre;
        g_sim[idx] = Sim;
        float nr = fmaf(pre, Sre, fmaf(-pim, Sim, ere));
        float ni = fmaf(pre, Sim, fmaf(pim, Sre, eim));
        Sre = nr; Sim = ni;
    }
}

// Phase C: full per-chunk scan with init state -> gelu(y + D*u) in fp32
__global__ __launch_bounds__(128) void s4_scan_out(
    const float* __restrict__ u, float* __restrict__ y,
    const float* __restrict__ cf, const float* __restrict__ Dv)
{
    const int b     = blockIdx.y;
    const int chunk = blockIdx.z;
    const int h0    = blockIdx.x * 32;
    const int tid   = threadIdx.x;
    const int w     = tid >> 5;
    const int lane  = tid & 31;
    const int hcol  = (w << 3) + (lane >> 2);
    const int mg    = (lane & 3) * 8;
    const int hh    = h0 + hcol;

    SCAN_COEF_LOAD(4)
    ull c2re2[4], c2in2[4];
#pragma unroll
    for (int p = 0; p < 4; p++) {
        int c0 = hh * NMODE + mg + 2 * p;
        c2re2[p] = packf(cf[4 * HN + c0], cf[4 * HN + c0 + 1]);
        c2in2[p] = packf(cf[5 * HN + c0], cf[5 * HN + c0 + 1]);
    }

    __shared__ float su[64 * 32];
    __shared__ float sy[64 * 32];
    __shared__ float sD[32];
    if (tid < 32) sD[tid] = Dv[h0 + tid];

    ull sre2[4], sim2[4];
    {
        size_t sidx = ((size_t)b * NCH + chunk) * HN + hh * NMODE + mg;
#pragma unroll
        for (int p = 0; p < 4; p++) {
            sre2[p] = packf(g_sre[sidx + 2 * p], g_sre[sidx + 2 * p + 1]);
            sim2[p] = packf(g_sim[sidx + 2 * p], g_sim[sidx + 2 * p + 1]);
        }
    }

    const size_t rbase = ((size_t)b * LSEQ + (size_t)chunk * CHL) * HDIM + h0;
    const float* ub = u + rbase;
    float*       yb = y + rbase;

    for (int l0 = 0; l0 < CHL; l0 += 64) {
        __syncthreads();
#pragma unroll
        for (int k = 0; k < 16; k++) {
            int e = tid + k * 128;
            su[e] = ub[(size_t)(l0 + (e >> 5)) * HDIM + (e & 31)];
        }
        __syncthreads();
#pragma unroll 2
        for (int i = 0; i < 64; i++) {
            ull uu2  = pack2(su[i * 32 + hcol]);
            ull cacc = 0ull;
#pragma unroll
            for (int p = 0; p < 4; p++) {
                ull mre = fma2(dBre2[p], uu2, 0ull);
                ull mim = fma2(dBim2[p], uu2, 0ull);
                ull nre = fma2(ndAim2[p], sim2[p], mre);
                nre     = fma2(dAre2[p],  sre2[p], nre);
                ull nim = fma2(dAim2[p],  sre2[p], mim);
                nim     = fma2(dAre2[p],  sim2[p], nim);
                sre2[p] = nre; sim2[p] = nim;
                cacc = fma2(c2re2[p], nre, cacc);
                cacc = fma2(c2in2[p], nim, cacc);
            }
            U2 cu; cu.u = cacc;
            float c = cu.f.x + cu.f.y;
            c += __shfl_xor_sync(0xffffffffu, c, 1);
            c += __shfl_xor_sync(0xffffffffu, c, 2);
            if ((lane & 3) == 0) sy[i * 32 + hcol] = c;
        }
        __syncthreads();
#pragma unroll
        for (int k = 0; k < 16; k++) {
            int e = tid + k * 128;
            float t = sy[e] + sD[e & 31] * su[e];
            yb[(size_t)(l0 + (e >> 5)) * HDIM + (e & 31)] = gelu_f(t);
        }
    }
}

// ---------------------------------------------------------------------------
// LayerNorm only (t -> h).  Warp per row of 256.
// ---------------------------------------------------------------------------
__global__ __launch_bounds__(256) void ln_only(
    const float* __restrict__ t, float* __restrict__ h,
    const float* __restrict__ lnw, const float* __restrict__ lnb)
{
    const int row  = blockIdx.x * 8 + (threadIdx.x >> 5);
    const int lane = threadIdx.x & 31;
    const float* tr = t + (size_t)row * HDIM;
    float*       hr = h + (size_t)row * HDIM;

    float tv[8];
    float s = 0.f, s2 = 0.f;
#pragma unroll
    for (int k = 0; k < 8; k++) {
        int c = lane + k * 32;
        float v = tr[c];
        tv[k] = v;
        s  += v;
        s2  = fmaf(v, v, s2);
    }
#pragma unroll
    for (int o = 16; o; o >>= 1) {
        s  += __shfl_xor_sync(0xffffffffu, s,  o);
        s2 += __shfl_xor_sync(0xffffffffu, s2, o);
    }
    float mean = s * (1.0f / 256.0f);
    float var  = fmaf(-mean, mean, s2 * (1.0f / 256.0f));
    float rs   = rsqrtf(var + 1e-5f);
#pragma unroll
    for (int k = 0; k < 8; k++) {
        int c = lane + k * 32;
        hr[c] = fmaf((tv[k] - mean) * rs, lnw[c], lnb[c]);
    }
}

// ---------------------------------------------------------------------------
// Decoder: out[M,10] = h[M,256] @ dec_w[256,10] + dec_b
// ---------------------------------------------------------------------------
__global__ __launch_bounds__(256) void decoder(
    const float* __restrict__ h, const float* __restrict__ wv,
    const float* __restrict__ bvec, float* __restrict__ out)
{
    __shared__ float sw[HDIM * DOUT];
    for (int i = threadIdx.x; i < HDIM * DOUT; i += 256) sw[i] = wv[i];
    __syncthreads();
    int o = blockIdx.x * 256 + threadIdx.x;
    int r = o / DOUT, n = o - r * DOUT;
    const float* hr = h + (size_t)r * HDIM;
    float s = bvec[n];
#pragma unroll 8
    for (int k = 0; k < HDIM; k++) s = fmaf(hr[k], sw[k * DOUT + n], s);
    out[o] = s;
}

// ---------------------------------------------------------------------------
extern "C" void kernel_launch(void* const* d_in, const int* in_sizes, int n_in,
                              void* d_out, int out_size)
{
    const float* x        = (const float*)d_in[0];
    const float* enc_w    = (const float*)d_in[1];
    const float* enc_b    = (const float*)d_in[2];
    const float* log_dt   = (const float*)d_in[3];
    const float* A_re_log = (const float*)d_in[4];
    const float* A_im     = (const float*)d_in[5];
    const float* B_re     = (const float*)d_in[6];
    const float* B_im     = (const float*)d_in[7];
    const float* C_re     = (const float*)d_in[8];
    const float* C_im     = (const float*)d_in[9];
    const float* Dp       = (const float*)d_in[10];
    const float* ln_w     = (const float*)d_in[11];
    const float* ln_b     = (const float*)d_in[12];
    const float* out_w    = (const float*)d_in[13];
    const float* out_b    = (const float*)d_in[14];
    const float* dec_w    = (const float*)d_in[15];
    const float* dec_b    = (const float*)d_in[16];
    float* outp = (float*)d_out;

    float *ph, *py, *pt, *pcf;
    __half *pwE, *pwl;
    cudaGetSymbolAddress((void**)&ph,  g_h);
    cudaGetSymbolAddress((void**)&py,  g_y);
    cudaGetSymbolAddress((void**)&pt,  g_t);
    cudaGetSymbolAddress((void**)&pcf, g_coef);
    cudaGetSymbolAddress((void**)&pwE, g_wt_enc);
    cudaGetSymbolAddress((void**)&pwl, g_wt);

    cudaFuncSetAttribute((const void*)mma_gemm<128, false>,
                         cudaFuncAttributeMaxDynamicSharedMemorySize, 49152);
    cudaFuncSetAttribute((const void*)mma_gemm<256, true>,
                         cudaFuncAttributeMaxDynamicSharedMemorySize, 49152);

    // Launch order puts s4_state(l=0) at slot 4 for ncu visibility.
    trans_w_f16<<<dim3(HDIM / 32, DIN / 32, 1), dim3(32, 8)>>>(enc_w, pwE,
                                                               DIN, HDIM);
    mma_gemm<128, false><<<dim3(2, MROWS / 128), 256, 49152>>>(
        x, pwE, enc_b, ph, HDIM, nullptr);
    prep_coef<<<(NL * HN + 255) / 256, 256>>>(log_dt, A_re_log, A_im,
                                              B_re, B_im, C_re, C_im);

    bool first = true;
    for (int l = 0; l < NL; l++) {
        const float* cfl = pcf + (size_t)l * 8 * HN;
        s4_state<<<dim3(HDIM / 32, BSZ, NCH - 1), 128>>>(ph, cfl);
        if (first) {
            trans_w_f16<<<dim3(2 * HDIM / 32, HDIM / 32, NL), dim3(32, 8)>>>(
                out_w, pwl, HDIM, 2 * HDIM);
            first = false;
        }
        s4_fix<<<(BSZ * HN + 255) / 256, 256>>>(cfl);
        s4_scan_out<<<dim3(HDIM / 32, BSZ, NCH), 128>>>(ph, py, cfl,
                                                        Dp + l * HDIM);
        mma_gemm<256, true><<<dim3(4, MROWS / 128), 256, 49152>>>(
            py, pwl + (size_t)l * 2 * HDIM * HDIM,
            out_b + l * 2 * HDIM, pt, 2 * HDIM, ph);
        ln_only<<<MROWS / 8, 256>>>(pt, ph, ln_w + l * HDIM, ln_b + l * HDIM);
    }

    decoder<<<(MROWS * DOUT) / 256, 256>>>(ph, dec_w, dec_b, outp);
}

// round 17
// speedup vs baseline: 1.3830x; 1.1235x over previous
#include <cuda_runtime.h>
#include <cuda_fp16.h>
#include <cstdint>

// ---------------------------------------------------------------------------
// S4D model forward:  encoder GEMM -> 4x( S4 scan+gelu -> GEMM(+GLU fused)
//                     -> LN ) -> decoder
// GEMMs: mma.sync m16n8k16 fp16, 2-pass (A hi/lo split-2, B single fp16),
//        fp32 accum, 2 CTAs/SM, B via cp.async.  Layer GEMM fuses
//        bias+GLU+residual in-epilogue.
// Scan:  time-chunked (8 chunks) 3-phase linear-recurrence decomposition in
//        the dB-normalized basis  s' = dA s' + u,  y = 2Re(C·dB · s')
//        -> 4 fma2/pair/step (state), 6 (state+output).
// ---------------------------------------------------------------------------

#define BSZ    32
#define LSEQ   1024
#define DIN    128
#define HDIM   256
#define NL     4
#define NMODE  32
#define DOUT   10
#define MROWS  (BSZ * LSEQ)          // 32768
#define HN     (HDIM * NMODE)        // 8192
#define NCH    8                     // time chunks
#define CHL    (LSEQ / NCH)          // 128 steps per chunk

// Scratch (device globals; no allocation allowed)
__device__ __align__(128) float g_h[MROWS * HDIM];
__device__ __align__(128) float g_y[MROWS * HDIM];
__device__ __align__(128) float g_t[MROWS * HDIM];   // GLU output (pre-LN)
__device__ __align__(128) float g_coef[NL * 6 * HN];
__device__ __align__(128) float g_sre[BSZ * NCH * HN];
__device__ __align__(128) float g_sim[BSZ * NCH * HN];
__device__ __align__(16) __half g_wt_enc[HDIM * DIN];          // [N=256][K=128]
__device__ __align__(16) __half g_wt[NL * 2 * HDIM * HDIM];    // [512][256] x4

typedef unsigned long long ull;

__device__ __forceinline__ ull pack2(float x) {
    ull r; asm("mov.b64 %0, {%1, %1};" : "=l"(r) : "f"(x)); return r;
}
__device__ __forceinline__ ull packf(float a, float b) {
    ull r; asm("mov.b64 %0, {%1, %2};" : "=l"(r) : "f"(a), "f"(b)); return r;
}
__device__ __forceinline__ ull fma2(ull a, ull b, ull c) {
    ull d; asm("fma.rn.f32x2 %0, %1, %2, %3;" : "=l"(d) : "l"(a), "l"(b), "l"(c)); return d;
}
union U2 { ull u; float2 f; };

__device__ __forceinline__ uint32_t smem_u32(const void* p) {
    uint32_t a;
    asm("{ .reg .u64 t; cvta.to.shared.u64 t, %1; cvt.u32.u64 %0, t; }"
        : "=r"(a) : "l"(p));
    return a;
}
__device__ __forceinline__ void ldsm4(uint32_t* r, uint32_t addr) {
    asm volatile("ldmatrix.sync.aligned.m8n8.x4.shared.b16 {%0,%1,%2,%3}, [%4];"
                 : "=r"(r[0]), "=r"(r[1]), "=r"(r[2]), "=r"(r[3]) : "r"(addr));
}
__device__ __forceinline__ void mma16816h(float* c, const uint32_t* a, const uint32_t* b) {
    asm volatile("mma.sync.aligned.m16n8k16.row.col.f32.f16.f16.f32 "
                 "{%0,%1,%2,%3}, {%4,%5,%6,%7}, {%8,%9}, {%0,%1,%2,%3};"
                 : "+f"(c[0]), "+f"(c[1]), "+f"(c[2]), "+f"(c[3])
                 : "r"(a[0]), "r"(a[1]), "r"(a[2]), "r"(a[3]), "r"(b[0]), "r"(b[1]));
}
__device__ __forceinline__ void cpasync16(uint32_t d, const void* s) {
    asm volatile("cp.async.cg.shared.global [%0], [%1], 16;" :: "r"(d), "l"(s));
}
__device__ __forceinline__ uint32_t pkhf(float a, float b) {
    uint32_t ha = __half_as_ushort(__float2half_rn(a));
    uint32_t hb = __half_as_ushort(__float2half_rn(b));
    return ha | (hb << 16);
}
__device__ __forceinline__ float sigm_f(float x) {
    return __fdividef(1.0f, 1.0f + __expf(-x));
}
// gelu(x) = x * sigmoid(1.5957691*(x + 0.044715 x^3)), MUFU exp + fast div
__device__ __forceinline__ float gelu_f(float x) {
    float t = fmaf(0.044715f * x * x, x, x);
    return __fdividef(x, 1.0f + __expf(-1.5957691216057308f * t));
}

// ---------------------------------------------------------------------------
// Discretization prep.  dB-normalized basis:
//   planes: 0 dAre, 1 dAim, 2 = 2Re(C·dB), 3 = -2Im(C·dB),
//           4/5 = (dA^CHL) re/im.
// ---------------------------------------------------------------------------
__global__ void prep_coef(const float* __restrict__ log_dt,
                          const float* __restrict__ A_re_log,
                          const float* __restrict__ A_im,
                          const float* __restrict__ B_re,
                          const float* __restrict__ B_im,
                          const float* __restrict__ C_re,
                          const float* __restrict__ C_im)
{
    int t = blockIdx.x * 256 + threadIdx.x;
    if (t >= NL * HN) return;
    int l  = t / HN;
    int hn = t - l * HN;
    int hh = hn / NMODE;

    float Are = -expf(A_re_log[t]);
    float Aim = A_im[t];
    float dt  = expf(log_dt[l * HDIM + hh]);
    float dre = dt * Are, dim = dt * Aim;
    float e   = expf(dre);
    float dAre = e * cosf(dim);
    float dAim = e * sinf(dim);
    float nre = dAre - 1.0f, nim = dAim;
    float inv = 1.0f / (Are * Are + Aim * Aim);
    float qre = (nre * Are + nim * Aim) * inv;
    float qim = (nim * Are - nre * Aim) * inv;
    float bre = B_re[t], bim = B_im[t];
    float dBre = bre * qre - bim * qim;
    float dBim = bre * qim + bim * qre;

    // fold dB into C:  C'' = C * dB
    float cre = C_re[t], cim = C_im[t];
    float cpre = cre * dBre - cim * dBim;
    float cpim = cre * dBim + cim * dBre;

    float eL = expf((float)CHL * dre);
    float cL = cosf((float)CHL * dim);
    float sL = sinf((float)CHL * dim);

    float* cf = g_coef + (size_t)l * 6 * HN;
    cf[0 * HN + hn] = dAre;
    cf[1 * HN + hn] = dAim;
    cf[2 * HN + hn] =  2.0f * cpre;
    cf[3 * HN + hn] = -2.0f * cpim;
    cf[4 * HN + hn] = eL * cL;
    cf[5 * HN + hn] = eL * sL;
}

// ---------------------------------------------------------------------------
// Weight transpose -> single fp16 plane:  W [K][N] fp32 -> WT [N][K] fp16
// ---------------------------------------------------------------------------
__global__ void trans_w_f16(const float* __restrict__ W,
                            __half* __restrict__ WT, int K, int N)
{
    __shared__ float t[32][33];
    int n0 = blockIdx.x * 32, k0 = blockIdx.y * 32;
    const float* Wp = W + (size_t)blockIdx.z * K * N;
    __half* Tp = WT + (size_t)blockIdx.z * K * N;
#pragma unroll
    for (int yy = 0; yy < 32; yy += 8)
        t[threadIdx.y + yy][threadIdx.x] =
            Wp[(size_t)(k0 + threadIdx.y + yy) * N + n0 + threadIdx.x];
    __syncthreads();
#pragma unroll
    for (int yy = 0; yy < 32; yy += 8) {
        float v = t[threadIdx.x][threadIdx.y + yy];
        Tp[(size_t)(n0 + threadIdx.y + yy) * K + k0 + threadIdx.x] =
            __float2half_rn(v);
    }
}

// ---------------------------------------------------------------------------
// fp16 2-pass tensor-core GEMM (2 CTAs/SM).
// GLU=false: C[M,N] = A@W + bias (encoder).
// GLU=true : CTA x owns a-cols [x*64,+64) and g-cols [256+x*64,+64);
//            epilogue t = (a+ba)*sigmoid(g+bg) + hres -> T[M,256].
// ---------------------------------------------------------------------------
template <int K, bool GLU>
__global__ __launch_bounds__(256, 2) void mma_gemm(
    const float* __restrict__ A,
    const __half* __restrict__ Bw,
    const float* __restrict__ bias,
    float* __restrict__ C, int N,
    const float* __restrict__ hres)
{
    constexpr int KCH  = K / 32;
    constexpr int STG  = 24576;
    extern __shared__ char sm[];
    const uint32_t sbase = smem_u32(sm);

    const int tid  = threadIdx.x;
    const int warp = tid >> 5, lane = tid & 31;
    const int wm = warp >> 1, wn = warp & 1;
    const size_t m0 = (size_t)blockIdx.y * 128;
    const int    n0 = blockIdx.x * 128;   // non-GLU col base
    const int    x64 = blockIdx.x * 64;   // GLU a-col base

    float4 afr[2][2];
    int usw[2];
#pragma unroll
    for (int i = 0; i < 2; i++) {
        int u = tid + i * 256;
        int row = u >> 2, c = u & 3;
        usw[i]  = row * 64 + ((c ^ ((row >> 1) & 3)) << 4);
    }

    auto ldgA = [&](int cs) {
#pragma unroll
        for (int i = 0; i < 2; i++) {
            int u = tid + i * 256;
            int row = u >> 2, c = u & 3;
            const float4* pa = (const float4*)(A + (m0 + row) * K + cs * 32 + c * 8);
            afr[i][0] = pa[0];
            afr[i][1] = pa[1];
        }
    };
    auto stsA = [&](int buf) {
        char* st = sm + buf * STG;
#pragma unroll
        for (int i = 0; i < 2; i++) {
            float f[8] = {afr[i][0].x, afr[i][0].y, afr[i][0].z, afr[i][0].w,
                          afr[i][1].x, afr[i][1].y, afr[i][1].z, afr[i][1].w};
            uint32_t hw[4], lw[4];
#pragma unroll
            for (int j = 0; j < 4; j++) {
                float a = f[2 * j], b = f[2 * j + 1];
                __half ha = __float2half_rn(a);
                __half hb = __float2half_rn(b);
                hw[j] = (uint32_t)__half_as_ushort(ha) |
                        ((uint32_t)__half_as_ushort(hb) << 16);
                lw[j] = pkhf(a - __half2float(ha), b - __half2float(hb));
            }
            *(uint4*)(st + usw[i])        = make_uint4(hw[0], hw[1], hw[2], hw[3]);
            *(uint4*)(st + 8192 + usw[i]) = make_uint4(lw[0], lw[1], lw[2], lw[3]);
        }
    };
    auto cpB = [&](int cs, int buf) {
        uint32_t st = sbase + buf * STG + 16384;
#pragma unroll
        for (int i = 0; i < 2; i++) {
            int u = tid + i * 256;
            int row = u >> 2, c = u & 3;
            int prow = GLU ? ((row < 64) ? (x64 + row) : (192 + x64 + row))
                           : (n0 + row);
            cpasync16(st + usw[i],
                      Bw + (size_t)prow * K + cs * 32 + c * 8);
        }
        asm volatile("cp.async.commit_group;");
    };

    float acc[2][8][4];
#pragma unroll
    for (int a = 0; a < 2; a++)
#pragma unroll
        for (int b = 0; b < 8; b++)
#pragma unroll
            for (int c = 0; c < 4; c++) acc[a][b][c] = 0.f;

    auto compute = [&](int buf) {
        uint32_t ab = sbase + buf * STG;
#pragma unroll
        for (int ks = 0; ks < 2; ks++) {
            uint32_t ah[2][4], al[2][4], bb[8][2];
#pragma unroll
            for (int mt = 0; mt < 2; mt++) {
                int r  = wm * 32 + mt * 16 + (lane & 15);
                int ch = ks * 2 + (lane >> 4);
                uint32_t addr = ab + r * 64 + ((ch ^ ((r >> 1) & 3)) << 4);
                ldsm4(ah[mt], addr);
                ldsm4(al[mt], addr + 8192);
            }
#pragma unroll
            for (int j = 0; j < 4; j++) {
                int r  = wn * 64 + j * 16 + (lane & 15);
                int ch = ks * 2 + (lane >> 4);
                uint32_t addr = ab + 16384 + r * 64 + ((ch ^ ((r >> 1) & 3)) << 4);
                uint32_t q[4];
                ldsm4(q, addr);
                bb[2 * j][0] = q[0]; bb[2 * j + 1][0] = q[1];
                bb[2 * j][1] = q[2]; bb[2 * j + 1][1] = q[3];
            }
#pragma unroll
            for (int mt = 0; mt < 2; mt++)
#pragma unroll
                for (int nt = 0; nt < 8; nt++) {
                    mma16816h(acc[mt][nt], ah[mt], bb[nt]);
                    mma16816h(acc[mt][nt], al[mt], bb[nt]);
                }
        }
    };

    // prologue: fill buffer 0
    ldgA(0);
    cpB(0, 0);
    stsA(0);
    if (KCH > 1) ldgA(1);
    asm volatile("cp.async.wait_group 0;" ::: "memory");
    __syncthreads();

    for (int c = 0; c < KCH; c++) {
        if (c + 1 < KCH) cpB(c + 1, (c + 1) & 1);
        compute(c & 1);
        if (c + 1 < KCH) {
            stsA((c + 1) & 1);
            if (c + 2 < KCH) ldgA(c + 2);
            asm volatile("cp.async.wait_group 0;" ::: "memory");
        }
        __syncthreads();
    }

    if (GLU) {
        // smem sigmoid-exchange: wn=1 warps hold g-cols, wn=0 hold a-cols.
        float* tb = (float*)sm;                 // [128][66] fp32
        if (wn == 1) {
#pragma unroll
            for (int mt = 0; mt < 2; mt++)
#pragma unroll
                for (int nt = 0; nt < 8; nt++) {
                    int r  = wm * 32 + mt * 16 + (lane >> 2);
                    int gc = nt * 8 + (lane & 3) * 2;
                    float bg0 = bias[256 + x64 + gc];
                    float bg1 = bias[256 + x64 + gc + 1];
                    tb[r * 66 + gc]           = sigm_f(acc[mt][nt][0] + bg0);
                    tb[r * 66 + gc + 1]       = sigm_f(acc[mt][nt][1] + bg1);
                    tb[(r + 8) * 66 + gc]     = sigm_f(acc[mt][nt][2] + bg0);
                    tb[(r + 8) * 66 + gc + 1] = sigm_f(acc[mt][nt][3] + bg1);
                }
        }
        __syncthreads();
        if (wn == 0) {
#pragma unroll
            for (int mt = 0; mt < 2; mt++)
#pragma unroll
                for (int nt = 0; nt < 8; nt++) {
                    int r  = wm * 32 + mt * 16 + (lane >> 2);
                    int ac = nt * 8 + (lane & 3) * 2;
                    float ba0 = bias[x64 + ac], ba1 = bias[x64 + ac + 1];
                    size_t go0 = (m0 + r) * HDIM + x64 + ac;
                    size_t go1 = (m0 + r + 8) * HDIM + x64 + ac;
                    float2 h0 = *(const float2*)(hres + go0);
                    float2 h1 = *(const float2*)(hres + go1);
                    float2 o0 = make_float2(
                        fmaf(acc[mt][nt][0] + ba0, tb[r * 66 + ac],       h0.x),
                        fmaf(acc[mt][nt][1] + ba1, tb[r * 66 + ac + 1],   h0.y));
                    float2 o1 = make_float2(
                        fmaf(acc[mt][nt][2] + ba0, tb[(r + 8) * 66 + ac],     h1.x),
                        fmaf(acc[mt][nt][3] + ba1, tb[(r + 8) * 66 + ac + 1], h1.y));
                    *(float2*)(C + go0) = o0;
                    *(float2*)(C + go1) = o1;
                }
        }
    } else {
#pragma unroll
        for (int mt = 0; mt < 2; mt++) {
#pragma unroll
            for (int nt = 0; nt < 8; nt++) {
                int r = (int)m0 + wm * 32 + mt * 16 + (lane >> 2);
                int n = n0 + wn * 64 + nt * 8 + (lane & 3) * 2;
                float b0 = bias[n], b1 = bias[n + 1];
                *(float2*)(C + (size_t)r * N + n) =
                    make_float2(acc[mt][nt][0] + b0, acc[mt][nt][1] + b1);
                *(float2*)(C + (size_t)(r + 8) * N + n) =
                    make_float2(acc[mt][nt][2] + b0, acc[mt][nt][3] + b1);
            }
        }
    }
}

// ---------------------------------------------------------------------------
// Scan lane mapping: block = 128 thr owns (batch, 32 chans, one time chunk).
// 4 lanes per channel, 8 modes per lane (4 packed pairs).
// dB-normalized recurrence:  s' = dA s' + u  (u real, injected directly).
// ---------------------------------------------------------------------------
#define SCAN_COEF_LOAD()                                                      \
    ull dAre2[4], dAim2[4], ndAim2[4];                                        \
    _Pragma("unroll")                                                         \
    for (int p = 0; p < 4; p++) {                                             \
        int c0 = hh * NMODE + mg + 2 * p;                                     \
        dAre2[p]  = packf(cf[0 * HN + c0], cf[0 * HN + c0 + 1]);              \
        dAim2[p]  = packf(cf[1 * HN + c0], cf[1 * HN + c0 + 1]);              \
        ndAim2[p] = packf(-cf[1 * HN + c0], -cf[1 * HN + c0 + 1]);            \
    }

// Phase A: local end-state per chunk (zero init), chunks 0..NCH-2
__global__ __launch_bounds__(128) void s4_state(
    const float* __restrict__ u, const float* __restrict__ cf)
{
    const int b     = blockIdx.y;
    const int chunk = blockIdx.z;
    const int h0    = blockIdx.x * 32;
    const int tid   = threadIdx.x;
    const int w     = tid >> 5;
    const int lane  = tid & 31;
    const int hcol  = (w << 3) + (lane >> 2);
    const int mg    = (lane & 3) * 8;
    const int hh    = h0 + hcol;

    SCAN_COEF_LOAD()

    __shared__ float su[64 * 32];
    ull sre2[4] = {0ull, 0ull, 0ull, 0ull};
    ull sim2[4] = {0ull, 0ull, 0ull, 0ull};

    const float* ub = u + ((size_t)b * LSEQ + (size_t)chunk * CHL) * HDIM + h0;

    for (int l0 = 0; l0 < CHL; l0 += 64) {
        __syncthreads();
#pragma unroll
        for (int k = 0; k < 16; k++) {
            int e = tid + k * 128;
            su[e] = ub[(size_t)(l0 + (e >> 5)) * HDIM + (e & 31)];
        }
        __syncthreads();
#pragma unroll 4
        for (int i = 0; i < 64; i++) {
            ull uu2 = pack2(su[i * 32 + hcol]);
#pragma unroll
            for (int p = 0; p < 4; p++) {
                ull nre = fma2(ndAim2[p], sim2[p], uu2);
                nre     = fma2(dAre2[p],  sre2[p], nre);
                ull nim = fma2(dAim2[p],  sre2[p], 0ull);
                nim     = fma2(dAre2[p],  sim2[p], nim);
                sre2[p] = nre; sim2[p] = nim;
            }
        }
    }
    size_t sidx = ((size_t)b * NCH + chunk) * HN + hh * NMODE + mg;
#pragma unroll
    for (int p = 0; p < 4; p++) {
        U2 r, q; r.u = sre2[p]; q.u = sim2[p];
        g_sre[sidx + 2 * p]     = r.f.x;
        g_sre[sidx + 2 * p + 1] = r.f.y;
        g_sim[sidx + 2 * p]     = q.f.x;
        g_sim[sidx + 2 * p + 1] = q.f.y;
    }
}

// Phase B: cross-chunk scan (in place): end-states -> init states
__global__ __launch_bounds__(256) void s4_fix(const float* __restrict__ cf)
{
    int t = blockIdx.x * 256 + threadIdx.x;
    if (t >= BSZ * HN) return;
    int b  = t / HN;
    int hn = t - b * HN;
    float pre = cf[4 * HN + hn], pim = cf[5 * HN + hn];
    float Sre = 0.f, Sim = 0.f;
#pragma unroll
    for (int c = 0; c < NCH; c++) {
        size_t idx = ((size_t)b * NCH + c) * HN + hn;
        float ere = 0.f, eim = 0.f;
        if (c < NCH - 1) { ere = g_sre[idx]; eim = g_sim[idx]; }
        g_sre[idx] = Sre;
        g_sim[idx] = Sim;
        float nr = fmaf(pre, Sre, fmaf(-pim, Sim, ere));
        float ni = fmaf(pre, Sim, fmaf(pim, Sre, eim));
        Sre = nr; Sim = ni;
    }
}

// Phase C: full per-chunk scan with init state -> gelu(y + D*u) in fp32
__global__ __launch_bounds__(128) void s4_scan_out(
    const float* __restrict__ u, float* __restrict__ y,
    const float* __restrict__ cf, const float* __restrict__ Dv)
{
    const int b     = blockIdx.y;
    const int chunk = blockIdx.z;
    const int h0    = blockIdx.x * 32;
    const int tid   = threadIdx.x;
    const int w     = tid >> 5;
    const int lane  = tid & 31;
    const int hcol  = (w << 3) + (lane >> 2);
    const int mg    = (lane & 3) * 8;
    const int hh    = h0 + hcol;

    SCAN_COEF_LOAD()
    ull c2re2[4], c2in2[4];
#pragma unroll
    for (int p = 0; p < 4; p++) {
        int c0 = hh * NMODE + mg + 2 * p;
        c2re2[p] = packf(cf[2 * HN + c0], cf[2 * HN + c0 + 1]);
        c2in2[p] = packf(cf[3 * HN + c0], cf[3 * HN + c0 + 1]);
    }

    __shared__ float su[64 * 32];
    __shared__ float sy[64 * 32];
    __shared__ float sD[32];
    if (tid < 32) sD[tid] = Dv[h0 + tid];

    ull sre2[4], sim2[4];
    {
        size_t sidx = ((size_t)b * NCH + chunk) * HN + hh * NMODE + mg;
#pragma unroll
        for (int p = 0; p < 4; p++) {
            sre2[p] = packf(g_sre[sidx + 2 * p], g_sre[sidx + 2 * p + 1]);
            sim2[p] = packf(g_sim[sidx + 2 * p], g_sim[sidx + 2 * p + 1]);
        }
    }

    const size_t rbase = ((size_t)b * LSEQ + (size_t)chunk * CHL) * HDIM + h0;
    const float* ub = u + rbase;
    float*       yb = y + rbase;

    for (int l0 = 0; l0 < CHL; l0 += 64) {
        __syncthreads();
#pragma unroll
        for (int k = 0; k < 16; k++) {
            int e = tid + k * 128;
            su[e] = ub[(size_t)(l0 + (e >> 5)) * HDIM + (e & 31)];
        }
        __syncthreads();
#pragma unroll 2
        for (int i = 0; i < 64; i++) {
            ull uu2  = pack2(su[i * 32 + hcol]);
            ull cacc = 0ull;
#pragma unroll
            for (int p = 0; p < 4; p++) {
                ull nre = fma2(ndAim2[p], sim2[p], uu2);
                nre     = fma2(dAre2[p],  sre2[p], nre);
                ull nim = fma2(dAim2[p],  sre2[p], 0ull);
                nim     = fma2(dAre2[p],  sim2[p], nim);
                sre2[p] = nre; sim2[p] = nim;
                cacc = fma2(c2re2[p], nre, cacc);
                cacc = fma2(c2in2[p], nim, cacc);
            }
            U2 cu; cu.u = cacc;
            float c = cu.f.x + cu.f.y;
            c += __shfl_xor_sync(0xffffffffu, c, 1);
            c += __shfl_xor_sync(0xffffffffu, c, 2);
            if ((lane & 3) == 0) sy[i * 32 + hcol] = c;
        }
        __syncthreads();
#pragma unroll
        for (int k = 0; k < 16; k++) {
            int e = tid + k * 128;
            float t = sy[e] + sD[e & 31] * su[e];
            yb[(size_t)(l0 + (e >> 5)) * HDIM + (e & 31)] = gelu_f(t);
        }
    }
}

// ---------------------------------------------------------------------------
// LayerNorm only (t -> h).  Warp per row of 256.
// ---------------------------------------------------------------------------
__global__ __launch_bounds__(256) void ln_only(
    const float* __restrict__ t, float* __restrict__ h,
    const float* __restrict__ lnw, const float* __restrict__ lnb)
{
    const int row  = blockIdx.x * 8 + (threadIdx.x >> 5);
    const int lane = threadIdx.x & 31;
    const float* tr = t + (size_t)row * HDIM;
    float*       hr = h + (size_t)row * HDIM;

    float tv[8];
    float s = 0.f, s2 = 0.f;
#pragma unroll
    for (int k = 0; k < 8; k++) {
        int c = lane + k * 32;
        float v = tr[c];
        tv[k] = v;
        s  += v;
        s2  = fmaf(v, v, s2);
    }
#pragma unroll
    for (int o = 16; o; o >>= 1) {
        s  += __shfl_xor_sync(0xffffffffu, s,  o);
        s2 += __shfl_xor_sync(0xffffffffu, s2, o);
    }
    float mean = s * (1.0f / 256.0f);
    float var  = fmaf(-mean, mean, s2 * (1.0f / 256.0f));
    float rs   = rsqrtf(var + 1e-5f);
#pragma unroll
    for (int k = 0; k < 8; k++) {
        int c = lane + k * 32;
        hr[c] = fmaf((tv[k] - mean) * rs, lnw[c], lnb[c]);
    }
}

// ---------------------------------------------------------------------------
// Decoder: out[M,10] = h[M,256] @ dec_w[256,10] + dec_b
// ---------------------------------------------------------------------------
__global__ __launch_bounds__(256) void decoder(
    const float* __restrict__ h, const float* __restrict__ wv,
    const float* __restrict__ bvec, float* __restrict__ out)
{
    __shared__ float sw[HDIM * DOUT];
    for (int i = threadIdx.x; i < HDIM * DOUT; i += 256) sw[i] = wv[i];
    __syncthreads();
    int o = blockIdx.x * 256 + threadIdx.x;
    int r = o / DOUT, n = o - r * DOUT;
    const float* hr = h + (size_t)r * HDIM;
    float s = bvec[n];
#pragma unroll 8
    for (int k = 0; k < HDIM; k++) s = fmaf(hr[k], sw[k * DOUT + n], s);
    out[o] = s;
}

// ---------------------------------------------------------------------------
extern "C" void kernel_launch(void* const* d_in, const int* in_sizes, int n_in,
                              void* d_out, int out_size)
{
    const float* x        = (const float*)d_in[0];
    const float* enc_w    = (const float*)d_in[1];
    const float* enc_b    = (const float*)d_in[2];
    const float* log_dt   = (const float*)d_in[3];
    const float* A_re_log = (const float*)d_in[4];
    const float* A_im     = (const float*)d_in[5];
    const float* B_re     = (const float*)d_in[6];
    const float* B_im     = (const float*)d_in[7];
    const float* C_re     = (const float*)d_in[8];
    const float* C_im     = (const float*)d_in[9];
    const float* Dp       = (const float*)d_in[10];
    const float* ln_w     = (const float*)d_in[11];
    const float* ln_b     = (const float*)d_in[12];
    const float* out_w    = (const float*)d_in[13];
    const float* out_b    = (const float*)d_in[14];
    const float* dec_w    = (const float*)d_in[15];
    const float* dec_b    = (const float*)d_in[16];
    float* outp = (float*)d_out;

    float *ph, *py, *pt, *pcf;
    __half *pwE, *pwl;
    cudaGetSymbolAddress((void**)&ph,  g_h);
    cudaGetSymbolAddress((void**)&py,  g_y);
    cudaGetSymbolAddress((void**)&pt,  g_t);
    cudaGetSymbolAddress((void**)&pcf, g_coef);
    cudaGetSymbolAddress((void**)&pwE, g_wt_enc);
    cudaGetSymbolAddress((void**)&pwl, g_wt);

    cudaFuncSetAttribute((const void*)mma_gemm<128, false>,
                         cudaFuncAttributeMaxDynamicSharedMemorySize, 49152);
    cudaFuncSetAttribute((const void*)mma_gemm<256, true>,
                         cudaFuncAttributeMaxDynamicSharedMemorySize, 49152);

    // Launch order keeps s4_state(l=0) at slot 4 for ncu visibility.
    trans_w_f16<<<dim3(HDIM / 32, DIN / 32, 1), dim3(32, 8)>>>(enc_w, pwE,
                                                               DIN, HDIM);
    mma_gemm<128, false><<<dim3(2, MROWS / 128), 256, 49152>>>(
        x, pwE, enc_b, ph, HDIM, nullptr);
    prep_coef<<<(NL * HN + 255) / 256, 256>>>(log_dt, A_re_log, A_im,
                                              B_re, B_im, C_re, C_im);

    bool first = true;
    for (int l = 0; l < NL; l++) {
        const float* cfl = pcf + (size_t)l * 6 * HN;
        s4_state<<<dim3(HDIM / 32, BSZ, NCH - 1), 128>>>(ph, cfl);
        if (first) {
            trans_w_f16<<<dim3(2 * HDIM / 32, HDIM / 32, NL), dim3(32, 8)>>>(
                out_w, pwl, HDIM, 2 * HDIM);
            first = false;
        }
        s4_fix<<<(BSZ * HN + 255) / 256, 256>>>(cfl);
        s4_scan_out<<<dim3(HDIM / 32, BSZ, NCH), 128>>>(ph, py, cfl,
                                                        Dp + l * HDIM);
        mma_gemm<256, true><<<dim3(4, MROWS / 128), 256, 49152>>>(
            py, pwl + (size_t)l * 2 * HDIM * HDIM,
            out_b + l * 2 * HDIM, pt, 2 * HDIM, ph);
        ln_only<<<MROWS / 8, 256>>>(pt, ph, ln_w + l * HDIM, ln_b + l * HDIM);
    }

    decoder<<<(MROWS * DOUT) / 256, 256>>>(ph, dec_w, dec_b, outp);
}